// round 12
// baseline (speedup 1.0000x reference)
#include <cuda_runtime.h>
#include <cuda_fp16.h>
#include <cstdint>

// ---------------- problem constants ----------------
constexpr int NN = 131072;
constexpr int EE = 262144;
constexpr int GG = 4096;
constexpr int D  = 768;
constexpr int HH = 4;
constexpr int HD = 192;
constexpr int ET = EE + NN;
constexpr int MAXE = 32;     // smem-cached edges per node (fallback beyond)

// ---------------- scratch (device globals) ----------------
__device__ __align__(256) __half g_xh[(size_t)NN * D];   // fp16: x, then h1 (in-place)
__device__ __align__(256) __half g_xwh[(size_t)NN * D];  // x @ W (fp16)
__device__ __align__(256) __half g_h2h[(size_t)NN * D];  // layer-2 output (fp16)
__device__ __align__(256) __half g_wth[D * D];           // W^T (K-major, fp16)
__device__ __align__(256) __half g_hgh[GG * D];          // pooled (fp16)
__device__ float g_asrc[NN * HH];
__device__ float g_adst[NN * HH];
__device__ int   g_indeg[NN];
__device__ int   g_cursor[NN];
__device__ int   g_rowptr[NN + 1];
__device__ int   g_scan[NN];
__device__ int   g_bsum[256];
__device__ int   g_csrc[ET];

// ---------------- helpers ----------------
__device__ __forceinline__ void cp16(uint32_t saddr, const void* g) {
    asm volatile("cp.async.cg.shared.global [%0], [%1], 16;" :: "r"(saddr), "l"(g));
}
__device__ __forceinline__ uint32_t smem_u32(const void* p) {
    uint32_t a;
    asm("{ .reg .u64 t; cvta.to.shared.u64 t, %1; cvt.u32.u64 %0, t; }" : "=r"(a) : "l"(p));
    return a;
}
#define CP_COMMIT()  asm volatile("cp.async.commit_group;" ::: "memory")
#define CP_WAIT(n)   asm volatile("cp.async.wait_group %0;" :: "n"(n) : "memory")

__device__ __forceinline__ void mma16(float* d, const uint32_t* a, const uint32_t* b) {
    asm volatile(
        "mma.sync.aligned.m16n8k16.row.col.f32.f16.f16.f32 "
        "{%0,%1,%2,%3}, {%4,%5,%6,%7}, {%8,%9}, {%0,%1,%2,%3};"
        : "+f"(d[0]), "+f"(d[1]), "+f"(d[2]), "+f"(d[3])
        : "r"(a[0]), "r"(a[1]), "r"(a[2]), "r"(a[3]), "r"(b[0]), "r"(b[1]));
}

// ---------------- CSR construction ----------------
__global__ void init_deg_kernel() {
    int i = blockIdx.x * blockDim.x + threadIdx.x;
    if (i < NN) {
        g_indeg[i] = 1;
#pragma unroll
        for (int h = 0; h < HH; h++) { g_asrc[i * HH + h] = 0.0f; g_adst[i * HH + h] = 0.0f; }
    }
}
__global__ void zero_attn_kernel() {
    int i = blockIdx.x * blockDim.x + threadIdx.x;
    if (i < NN * HH) { g_asrc[i] = 0.0f; g_adst[i] = 0.0f; }
}
__global__ void count_deg_kernel(const int* __restrict__ ei) {
    int e = blockIdx.x * blockDim.x + threadIdx.x;
    if (e < EE) atomicAdd(&g_indeg[ei[EE + e]], 1);
}
__device__ __forceinline__ int block_incl_scan(int v, int* warp_sums) {
    const unsigned full = 0xffffffffu;
    int lane = threadIdx.x & 31, w = threadIdx.x >> 5, nw = blockDim.x >> 5;
#pragma unroll
    for (int o = 1; o < 32; o <<= 1) { int u = __shfl_up_sync(full, v, o); if (lane >= o) v += u; }
    if (lane == 31) warp_sums[w] = v;
    __syncthreads();
    if (w == 0) {
        int s = (lane < nw) ? warp_sums[lane] : 0;
#pragma unroll
        for (int o = 1; o < 32; o <<= 1) { int u = __shfl_up_sync(full, s, o); if (lane >= o) s += u; }
        if (lane < nw) warp_sums[lane] = s;
    }
    __syncthreads();
    if (w > 0) v += warp_sums[w - 1];
    return v;
}
__global__ void scan_phase1_kernel() {
    __shared__ int ws[32];
    int gid = blockIdx.x * 1024 + threadIdx.x;
    int incl = block_incl_scan(g_indeg[gid], ws);
    g_scan[gid] = incl;
    if (threadIdx.x == 1023) g_bsum[blockIdx.x] = incl;
}
__global__ void scan_phase2_kernel() {
    __shared__ int ws[32];
    int v = g_bsum[threadIdx.x];
    int incl = block_incl_scan(v, ws);
    g_bsum[threadIdx.x] = incl - v;
}
__global__ void scan_phase3_kernel() {
    int gid = blockIdx.x * blockDim.x + threadIdx.x;
    if (gid < NN) {
        g_rowptr[gid + 1] = g_scan[gid] + g_bsum[gid >> 10];
        if (gid == 0) g_rowptr[0] = 0;
    }
}
__global__ void selfloop_init_kernel() {
    int i = blockIdx.x * blockDim.x + threadIdx.x;
    if (i < NN) { int p = g_rowptr[i]; g_csrc[p] = i; g_cursor[i] = p + 1; }
}
__global__ void scatter_edges_kernel(const int* __restrict__ ei) {
    int e = blockIdx.x * blockDim.x + threadIdx.x;
    if (e < EE) { int p = atomicAdd(&g_cursor[ei[EE + e]], 1); g_csrc[p] = ei[e]; }
}

// ---------------- fp32 -> fp16 conversion pass ----------------
__global__ void conv_half_kernel(const float4* __restrict__ in, __half2* __restrict__ out) {
    int i = blockIdx.x * blockDim.x + threadIdx.x;
    float4 v = in[i];
    out[2 * i]     = __floats2half2_rn(v.x, v.y);
    out[2 * i + 1] = __floats2half2_rn(v.z, v.w);
}

// ---------------- transpose 768x768 -> fp16 K-major ----------------
__global__ void transpose768_kernel(const float* __restrict__ W, __half* __restrict__ WT) {
    __shared__ float t[32][33];
    int bx = blockIdx.x * 32, by = blockIdx.y * 32;
    for (int i = threadIdx.y; i < 32; i += 8)
        t[i][threadIdx.x] = W[(size_t)(by + i) * D + bx + threadIdx.x];
    __syncthreads();
    for (int i = threadIdx.y; i < 32; i += 8)
        WT[(size_t)(bx + i) * D + by + threadIdx.x] = __float2half_rn(t[threadIdx.x][i]);
}

// ---------------- fp16 mma GEMM + fused attention-score epilogue ----------------
constexpr int BK   = 64;
constexpr int KSTG = D / BK;                      // 12
constexpr int RS   = 72;
constexpr int TILE_H  = 128 * RS;
constexpr int STAGE_H = 2 * TILE_H;
constexpr int SM_GEMM = 3 * STAGE_H * 2;          // 110,592 bytes

__global__ __launch_bounds__(256, 2) void mma_gemm_kernel(
    const __half* __restrict__ A, const __half* __restrict__ BT,
    float* __restrict__ Cf, __half* __restrict__ Ch, const float* __restrict__ bias,
    const float* __restrict__ att_s, const float* __restrict__ att_d,
    float* __restrict__ asrc, float* __restrict__ adst)
{
    extern __shared__ __half smh[];
    const int tid  = threadIdx.x;
    const int wid  = tid >> 5, lane = tid & 31;
    const int gid  = lane >> 2, tig = lane & 3;
    const int m0   = blockIdx.y * 128;
    const int n0   = blockIdx.x * 128;
    const int wm   = (wid & 1) * 64;
    const int wn   = (wid >> 1) * 32;

    const __half* ga = A  + (size_t)m0 * D;
    const __half* gb = BT + (size_t)n0 * D;
    const uint32_t sm_u = smem_u32(smh);

    auto load_stage = [&](int buf, int ks) {
        int k0 = ks * BK;
        uint32_t abase = sm_u + (uint32_t)buf * STAGE_H * 2;
        uint32_t bbase = abase + TILE_H * 2;
#pragma unroll
        for (int t = tid; t < 1024; t += 256) {
            int row = t >> 3, c = t & 7;
            uint32_t off = (uint32_t)(row * RS + c * 8) * 2;
            cp16(abase + off, ga + (size_t)row * D + k0 + c * 8);
            cp16(bbase + off, gb + (size_t)row * D + k0 + c * 8);
        }
        CP_COMMIT();
    };

    float acc[4][4][4];
#pragma unroll
    for (int i = 0; i < 4; i++)
#pragma unroll
        for (int j = 0; j < 4; j++)
#pragma unroll
            for (int q = 0; q < 4; q++) acc[i][j][q] = 0.0f;

    load_stage(0, 0);
    load_stage(1, 1);

    for (int s = 0; s < KSTG; ++s) {
        int buf = s % 3;
        if (s < KSTG - 1) CP_WAIT(1); else CP_WAIT(0);
        __syncthreads();

        const __half* Ab = smh + buf * STAGE_H + (wm + gid) * RS;
        const __half* Bb = smh + buf * STAGE_H + TILE_H + (wn + gid) * RS;
#pragma unroll
        for (int kk = 0; kk < 4; ++kk) {
            uint32_t af[4][4], bf[4][2];
#pragma unroll
            for (int i = 0; i < 4; ++i) {
                const __half* p = Ab + i * (16 * RS) + kk * 16 + tig * 2;
                af[i][0] = *(const uint32_t*)(p);
                af[i][1] = *(const uint32_t*)(p + 8 * RS);
                af[i][2] = *(const uint32_t*)(p + 8);
                af[i][3] = *(const uint32_t*)(p + 8 * RS + 8);
            }
#pragma unroll
            for (int j = 0; j < 4; ++j) {
                const __half* p = Bb + j * (8 * RS) + kk * 16 + tig * 2;
                bf[j][0] = *(const uint32_t*)(p);
                bf[j][1] = *(const uint32_t*)(p + 8);
            }
#pragma unroll
            for (int i = 0; i < 4; ++i)
#pragma unroll
                for (int j = 0; j < 4; ++j)
                    mma16(acc[i][j], af[i], bf[j]);
        }
        if (s + 2 < KSTG) load_stage((s + 2) % 3, s + 2);
    }

    if (att_s) {
        const unsigned full = 0xffffffffu;
        const int h = (n0 + wn) / HD;
        float asv[8], adv[8];
#pragma unroll
        for (int j = 0; j < 4; ++j) {
            int cb = n0 + wn + j * 8 + tig * 2;
            asv[j * 2 + 0] = att_s[cb];     asv[j * 2 + 1] = att_s[cb + 1];
            adv[j * 2 + 0] = att_d[cb];     adv[j * 2 + 1] = att_d[cb + 1];
        }
        float ps[8], pd[8];
#pragma unroll
        for (int i = 0; i < 4; ++i) {
            float s0 = 0, s1 = 0, d0 = 0, d1 = 0;
#pragma unroll
            for (int j = 0; j < 4; ++j) {
                s0 += acc[i][j][0] * asv[j * 2] + acc[i][j][1] * asv[j * 2 + 1];
                s1 += acc[i][j][2] * asv[j * 2] + acc[i][j][3] * asv[j * 2 + 1];
                d0 += acc[i][j][0] * adv[j * 2] + acc[i][j][1] * adv[j * 2 + 1];
                d1 += acc[i][j][2] * adv[j * 2] + acc[i][j][3] * adv[j * 2 + 1];
            }
            ps[i * 2] = s0; ps[i * 2 + 1] = s1; pd[i * 2] = d0; pd[i * 2 + 1] = d1;
        }
#pragma unroll
        for (int o = 1; o <= 2; o <<= 1)
#pragma unroll
            for (int k = 0; k < 8; ++k) {
                ps[k] += __shfl_xor_sync(full, ps[k], o);
                pd[k] += __shfl_xor_sync(full, pd[k], o);
            }
        if (tig == 0) {
#pragma unroll
            for (int i = 0; i < 4; ++i) {
                int r0 = m0 + wm + i * 16 + gid;
                atomicAdd(&asrc[r0 * HH + h],       ps[i * 2]);
                atomicAdd(&asrc[(r0 + 8) * HH + h], ps[i * 2 + 1]);
                atomicAdd(&adst[r0 * HH + h],       pd[i * 2]);
                atomicAdd(&adst[(r0 + 8) * HH + h], pd[i * 2 + 1]);
            }
        }
    }

    if (Ch) {
#pragma unroll
        for (int i = 0; i < 4; ++i) {
            int r = m0 + wm + i * 16 + gid;
#pragma unroll
            for (int j = 0; j < 4; ++j) {
                int cb = n0 + wn + j * 8 + tig * 2;
                *(__half2*)&Ch[(size_t)r * D + cb]       = __floats2half2_rn(acc[i][j][0], acc[i][j][1]);
                *(__half2*)&Ch[(size_t)(r + 8) * D + cb] = __floats2half2_rn(acc[i][j][2], acc[i][j][3]);
            }
        }
    } else {
#pragma unroll
        for (int i = 0; i < 4; ++i) {
            int r = m0 + wm + i * 16 + gid;
#pragma unroll
            for (int j = 0; j < 4; ++j) {
                int cb = n0 + wn + j * 8 + tig * 2;
                float bx = bias ? bias[cb] : 0.0f, by = bias ? bias[cb + 1] : 0.0f;
                float2 v0 = { acc[i][j][0] + bx, acc[i][j][1] + by };
                float2 v1 = { acc[i][j][2] + bx, acc[i][j][3] + by };
                *(float2*)&Cf[(size_t)r * D + cb]       = v0;
                *(float2*)&Cf[(size_t)(r + 8) * D + cb] = v1;
            }
        }
    }
}

__device__ __forceinline__ float leaky02(float e) { return e > 0.0f ? e : 0.2f * e; }

// ---------------- fused GAT layer: smem score cache + 4-wide batched gather ----------------
__global__ __launch_bounds__(256) void gat_fused_kernel(
    const float* __restrict__ bias, const float* __restrict__ gamma,
    const float* __restrict__ beta, const __half* h_res, __half* h_out)
{
    __shared__ float ews_all[8 * 4 * MAXE];
    const unsigned full = 0xffffffffu;
    int wid  = threadIdx.x >> 5;
    int lane = threadIdx.x & 31;
    int n = blockIdx.x * 8 + wid;
    float* ews = &ews_all[wid * 4 * MAXE];

    int beg = g_rowptr[n], end = g_rowptr[n + 1];
    float4 ad = *(const float4*)&g_adst[n * 4];

    // pass 1: e = leaky(asrc + adst), cache to smem, max-reduce
    float m0 = -1e30f, m1 = -1e30f, m2 = -1e30f, m3 = -1e30f;
    for (int p = beg + lane; p < end; p += 32) {
        int s = g_csrc[p];
        float4 sv = *(const float4*)&g_asrc[s * 4];
        float e0 = leaky02(sv.x + ad.x), e1 = leaky02(sv.y + ad.y);
        float e2 = leaky02(sv.z + ad.z), e3 = leaky02(sv.w + ad.w);
        int e = p - beg;
        if (e < MAXE) {
            ews[e] = e0; ews[MAXE + e] = e1; ews[2 * MAXE + e] = e2; ews[3 * MAXE + e] = e3;
        }
        m0 = fmaxf(m0, e0); m1 = fmaxf(m1, e1); m2 = fmaxf(m2, e2); m3 = fmaxf(m3, e3);
    }
#pragma unroll
    for (int o = 16; o; o >>= 1) {
        m0 = fmaxf(m0, __shfl_xor_sync(full, m0, o));
        m1 = fmaxf(m1, __shfl_xor_sync(full, m1, o));
        m2 = fmaxf(m2, __shfl_xor_sync(full, m2, o));
        m3 = fmaxf(m3, __shfl_xor_sync(full, m3, o));
    }

    // pass 2: ex = exp(e - m) in place, sum-reduce
    float d0 = 0, d1 = 0, d2 = 0, d3 = 0;
    for (int p = beg + lane; p < end; p += 32) {
        int e = p - beg;
        float e0, e1, e2, e3;
        if (e < MAXE) {
            e0 = ews[e]; e1 = ews[MAXE + e]; e2 = ews[2 * MAXE + e]; e3 = ews[3 * MAXE + e];
        } else {
            int s = g_csrc[p];
            float4 sv = *(const float4*)&g_asrc[s * 4];
            e0 = leaky02(sv.x + ad.x); e1 = leaky02(sv.y + ad.y);
            e2 = leaky02(sv.z + ad.z); e3 = leaky02(sv.w + ad.w);
        }
        float x0 = __expf(e0 - m0), x1 = __expf(e1 - m1);
        float x2 = __expf(e2 - m2), x3 = __expf(e3 - m3);
        if (e < MAXE) {
            ews[e] = x0; ews[MAXE + e] = x1; ews[2 * MAXE + e] = x2; ews[3 * MAXE + e] = x3;
        }
        d0 += x0; d1 += x1; d2 += x2; d3 += x3;
    }
#pragma unroll
    for (int o = 16; o; o >>= 1) {
        d0 += __shfl_xor_sync(full, d0, o);
        d1 += __shfl_xor_sync(full, d1, o);
        d2 += __shfl_xor_sync(full, d2, o);
        d3 += __shfl_xor_sync(full, d3, o);
    }
    float i0 = 1.0f / d0, i1 = 1.0f / d1, i2 = 1.0f / d2, i3 = 1.0f / d3;
    __syncwarp();   // cross-lane smem visibility for pass 3

    // pass 3: 4-wide batched gather (MLP = 12) + weighted accumulate
    float acc[3][8];
#pragma unroll
    for (int i = 0; i < 3; i++)
#pragma unroll
        for (int k = 0; k < 8; k++) acc[i][k] = 0.0f;

    for (int p0 = beg; p0 < end; p0 += 4) {
        int cnt = end - p0; if (cnt > 4) cnt = 4;
        uint4 f[4][3];
#pragma unroll
        for (int e = 0; e < 4; ++e) {
            if (e < cnt) {
                const uint4* rp = (const uint4*)(g_xwh + (size_t)g_csrc[p0 + e] * D);
                f[e][0] = __ldg(&rp[lane]);
                f[e][1] = __ldg(&rp[32 + lane]);
                f[e][2] = __ldg(&rp[64 + lane]);
            }
        }
#pragma unroll
        for (int e = 0; e < 4; ++e) {
            if (e < cnt) {
                int es = p0 + e - beg;
                float a0, a1, a2, a3;
                if (es < MAXE) {
                    a0 = ews[es] * i0;            a1 = ews[MAXE + es] * i1;
                    a2 = ews[2 * MAXE + es] * i2; a3 = ews[3 * MAXE + es] * i3;
                } else {
                    int s = g_csrc[p0 + e];
                    float4 sv = *(const float4*)&g_asrc[s * 4];
                    a0 = __expf(leaky02(sv.x + ad.x) - m0) * i0;
                    a1 = __expf(leaky02(sv.y + ad.y) - m1) * i1;
                    a2 = __expf(leaky02(sv.z + ad.z) - m2) * i2;
                    a3 = __expf(leaky02(sv.w + ad.w) - m3) * i3;
                }
#pragma unroll
                for (int i = 0; i < 3; i++) {
                    int idx = i * 256 + lane * 8;
                    int h = idx / HD;
                    float a = (h == 0) ? a0 : (h == 1) ? a1 : (h == 2) ? a2 : a3;
                    uint4 v = f[e][i];
                    float2 q0 = __half22float2(*(__half2*)&v.x);
                    float2 q1 = __half22float2(*(__half2*)&v.y);
                    float2 q2 = __half22float2(*(__half2*)&v.z);
                    float2 q3 = __half22float2(*(__half2*)&v.w);
                    acc[i][0] = fmaf(a, q0.x, acc[i][0]);
                    acc[i][1] = fmaf(a, q0.y, acc[i][1]);
                    acc[i][2] = fmaf(a, q1.x, acc[i][2]);
                    acc[i][3] = fmaf(a, q1.y, acc[i][3]);
                    acc[i][4] = fmaf(a, q2.x, acc[i][4]);
                    acc[i][5] = fmaf(a, q2.y, acc[i][5]);
                    acc[i][6] = fmaf(a, q3.x, acc[i][6]);
                    acc[i][7] = fmaf(a, q3.y, acc[i][7]);
                }
            }
        }
    }

    // +bias, LN stats
    float s1 = 0.0f;
#pragma unroll
    for (int i = 0; i < 3; i++) {
        int idx = i * 256 + lane * 8;
        float4 b0 = *(const float4*)(bias + idx);
        float4 b1 = *(const float4*)(bias + idx + 4);
        acc[i][0] += b0.x; acc[i][1] += b0.y; acc[i][2] += b0.z; acc[i][3] += b0.w;
        acc[i][4] += b1.x; acc[i][5] += b1.y; acc[i][6] += b1.z; acc[i][7] += b1.w;
#pragma unroll
        for (int k = 0; k < 8; k++) s1 += acc[i][k];
    }
#pragma unroll
    for (int o = 16; o; o >>= 1) s1 += __shfl_xor_sync(full, s1, o);
    float mu = s1 * (1.0f / 768.0f);

    float s2 = 0.0f;
#pragma unroll
    for (int i = 0; i < 3; i++)
#pragma unroll
        for (int k = 0; k < 8; k++) { float dv = acc[i][k] - mu; s2 += dv * dv; }
#pragma unroll
    for (int o = 16; o; o >>= 1) s2 += __shfl_xor_sync(full, s2, o);
    float rstd = rsqrtf(s2 * (1.0f / 768.0f) + 1e-5f);

#pragma unroll
    for (int i = 0; i < 3; i++) {
        int idx = i * 256 + lane * 8;
        float4 g0 = *(const float4*)(gamma + idx);
        float4 g1 = *(const float4*)(gamma + idx + 4);
        float4 e0 = *(const float4*)(beta + idx);
        float4 e1 = *(const float4*)(beta + idx + 4);
        uint4 rv = *(const uint4*)(h_res + (size_t)n * D + idx);
        float2 r0 = __half22float2(*(__half2*)&rv.x);
        float2 r1 = __half22float2(*(__half2*)&rv.y);
        float2 r2 = __half22float2(*(__half2*)&rv.z);
        float2 r3 = __half22float2(*(__half2*)&rv.w);
        float o0 = fmaxf(fmaf((acc[i][0] - mu) * rstd, g0.x, e0.x), 0.0f) + r0.x;
        float o1 = fmaxf(fmaf((acc[i][1] - mu) * rstd, g0.y, e0.y), 0.0f) + r0.y;
        float o2 = fmaxf(fmaf((acc[i][2] - mu) * rstd, g0.z, e0.z), 0.0f) + r1.x;
        float o3 = fmaxf(fmaf((acc[i][3] - mu) * rstd, g0.w, e0.w), 0.0f) + r1.y;
        float o4 = fmaxf(fmaf((acc[i][4] - mu) * rstd, g1.x, e1.x), 0.0f) + r2.x;
        float o5 = fmaxf(fmaf((acc[i][5] - mu) * rstd, g1.y, e1.y), 0.0f) + r2.y;
        float o6 = fmaxf(fmaf((acc[i][6] - mu) * rstd, g1.z, e1.z), 0.0f) + r3.x;
        float o7 = fmaxf(fmaf((acc[i][7] - mu) * rstd, g1.w, e1.w), 0.0f) + r3.y;
        uint4 hv;
        *(__half2*)&hv.x = __floats2half2_rn(o0, o1);
        *(__half2*)&hv.y = __floats2half2_rn(o2, o3);
        *(__half2*)&hv.z = __floats2half2_rn(o4, o5);
        *(__half2*)&hv.w = __floats2half2_rn(o6, o7);
        *(uint4*)(h_out + (size_t)n * D + idx) = hv;
    }
}

// ---------------- mean pooling (fp16 in, fp16 out) ----------------
__global__ void pool_mean_kernel() {
    int g = blockIdx.x;
    const __half2* base = (const __half2*)(g_h2h + (size_t)g * 32 * D);
    for (int d2 = threadIdx.x; d2 < D / 2; d2 += blockDim.x) {
        float sx = 0.0f, sy = 0.0f;
#pragma unroll
        for (int r = 0; r < 32; r++) {
            float2 v = __half22float2(base[r * (D / 2) + d2]);
            sx += v.x; sy += v.y;
        }
        ((__half2*)g_hgh)[g * (D / 2) + d2] = __floats2half2_rn(sx * (1.0f / 32.0f), sy * (1.0f / 32.0f));
    }
}

// ---------------- launcher ----------------
extern "C" void kernel_launch(void* const* d_in, const int* in_sizes, int n_in,
                              void* d_out, int out_size)
{
    const float* x   = (const float*)d_in[0];
    const int*   ei  = (const int*)d_in[1];
    const float* W1  = (const float*)d_in[3];
    const float* as1 = (const float*)d_in[4];
    const float* ad1 = (const float*)d_in[5];
    const float* b1  = (const float*)d_in[6];
    const float* g1  = (const float*)d_in[7];
    const float* be1 = (const float*)d_in[8];
    const float* W2  = (const float*)d_in[9];
    const float* as2 = (const float*)d_in[10];
    const float* ad2 = (const float*)d_in[11];
    const float* b2  = (const float*)d_in[12];
    const float* g2  = (const float*)d_in[13];
    const float* be2 = (const float*)d_in[14];
    const float* Wo  = (const float*)d_in[15];
    const float* bo  = (const float*)d_in[16];
    float* out = (float*)d_out;

    float *p_as, *p_ad;
    __half *p_xh, *p_xwh, *p_h2h, *p_wth, *p_hgh;
    cudaGetSymbolAddress((void**)&p_xh,  g_xh);
    cudaGetSymbolAddress((void**)&p_xwh, g_xwh);
    cudaGetSymbolAddress((void**)&p_h2h, g_h2h);
    cudaGetSymbolAddress((void**)&p_wth, g_wth);
    cudaGetSymbolAddress((void**)&p_hgh, g_hgh);
    cudaGetSymbolAddress((void**)&p_as,  g_asrc);
    cudaGetSymbolAddress((void**)&p_ad,  g_adst);

    cudaFuncSetAttribute(mma_gemm_kernel,
                         cudaFuncAttributeMaxDynamicSharedMemorySize, SM_GEMM);

    dim3 tgrid(24, 24), tblk(32, 8);
    dim3 ggrid(D / 128, NN / 128);     // (6, 1024)

    conv_half_kernel<<<(NN * (D / 4)) / 256, 256>>>((const float4*)x, (__half2*)p_xh); // 0
    transpose768_kernel<<<tgrid, tblk>>>(W1, p_wth);                                    // 1
    init_deg_kernel<<<NN / 256, 256>>>();                                               // 2
    mma_gemm_kernel<<<ggrid, 256, SM_GEMM>>>(p_xh, p_wth, nullptr, p_xwh, nullptr,      // 3
                                             as1, ad1, p_as, p_ad);
    count_deg_kernel<<<EE / 256, 256>>>(ei);
    scan_phase1_kernel<<<NN / 1024, 1024>>>();
    scan_phase2_kernel<<<1, 128>>>();
    scan_phase3_kernel<<<(NN + 255) / 256, 256>>>();
    selfloop_init_kernel<<<NN / 256, 256>>>();
    scatter_edges_kernel<<<EE / 256, 256>>>(ei);

    // layer 1: residual fp16 x (in g_xh), write h1 fp16 IN PLACE into g_xh
    gat_fused_kernel<<<NN / 8, 256>>>(b1, g1, be1, p_xh, p_xh);

    // layer 2
    zero_attn_kernel<<<(NN * HH) / 256, 256>>>();
    transpose768_kernel<<<tgrid, tblk>>>(W2, p_wth);
    mma_gemm_kernel<<<ggrid, 256, SM_GEMM>>>(p_xh, p_wth, nullptr, p_xwh, nullptr,
                                             as2, ad2, p_as, p_ad);
    gat_fused_kernel<<<NN / 8, 256>>>(b2, g2, be2, p_xh, p_h2h);

    // pool + output projection
    pool_mean_kernel<<<GG, 256>>>();
    transpose768_kernel<<<tgrid, tblk>>>(Wo, p_wth);
    mma_gemm_kernel<<<dim3(D / 128, GG / 128), 256, SM_GEMM>>>(p_hgh, p_wth, out, nullptr, bo,
                                                               nullptr, nullptr, nullptr, nullptr);
}

// round 13
// speedup vs baseline: 1.1311x; 1.1311x over previous
#include <cuda_runtime.h>
#include <cuda_fp16.h>
#include <cstdint>

// ---------------- problem constants ----------------
constexpr int NN = 131072;
constexpr int EE = 262144;
constexpr int GG = 4096;
constexpr int D  = 768;
constexpr int HH = 4;
constexpr int HD = 192;
constexpr int ET = EE + NN;
constexpr int MAXE = 32;

// ---------------- scratch (device globals) ----------------
__device__ __align__(256) __half g_xh[(size_t)NN * D];   // fp16: x, then h1 (in-place)
__device__ __align__(256) __half g_xwh[(size_t)NN * D];  // x @ W (fp16)
__device__ __align__(256) __half g_wth[D * D];           // W^T (K-major, fp16)
__device__ __align__(256) __half g_hgh[GG * D];          // pooled (fp16)
__device__ float g_asrc[NN * HH];
__device__ float g_adst[NN * HH];
__device__ int   g_indeg[NN];
__device__ int   g_cursor[NN];
__device__ int   g_rowptr[NN + 1];
__device__ int   g_scan[NN];
__device__ int   g_bsum[256];
__device__ int   g_csrc[ET];

// ---------------- helpers ----------------
__device__ __forceinline__ void cp16(uint32_t saddr, const void* g) {
    asm volatile("cp.async.cg.shared.global [%0], [%1], 16;" :: "r"(saddr), "l"(g));
}
__device__ __forceinline__ uint32_t smem_u32(const void* p) {
    uint32_t a;
    asm("{ .reg .u64 t; cvta.to.shared.u64 t, %1; cvt.u32.u64 %0, t; }" : "=r"(a) : "l"(p));
    return a;
}
#define CP_COMMIT()  asm volatile("cp.async.commit_group;" ::: "memory")
#define CP_WAIT(n)   asm volatile("cp.async.wait_group %0;" :: "n"(n) : "memory")

__device__ __forceinline__ void mma16(float* d, const uint32_t* a, const uint32_t* b) {
    asm volatile(
        "mma.sync.aligned.m16n8k16.row.col.f32.f16.f16.f32 "
        "{%0,%1,%2,%3}, {%4,%5,%6,%7}, {%8,%9}, {%0,%1,%2,%3};"
        : "+f"(d[0]), "+f"(d[1]), "+f"(d[2]), "+f"(d[3])
        : "r"(a[0]), "r"(a[1]), "r"(a[2]), "r"(a[3]), "r"(b[0]), "r"(b[1]));
}

// ---------------- CSR construction ----------------
__global__ void init_deg_kernel() {
    int i = blockIdx.x * blockDim.x + threadIdx.x;
    if (i < NN) {
        g_indeg[i] = 1;
#pragma unroll
        for (int h = 0; h < HH; h++) { g_asrc[i * HH + h] = 0.0f; g_adst[i * HH + h] = 0.0f; }
    }
}
__global__ void zero_attn_kernel() {
    int i = blockIdx.x * blockDim.x + threadIdx.x;
    if (i < NN * HH) { g_asrc[i] = 0.0f; g_adst[i] = 0.0f; }
}
__global__ void count_deg_kernel(const int* __restrict__ ei) {
    int e = blockIdx.x * blockDim.x + threadIdx.x;
    if (e < EE) atomicAdd(&g_indeg[ei[EE + e]], 1);
}
__device__ __forceinline__ int block_incl_scan(int v, int* warp_sums) {
    const unsigned full = 0xffffffffu;
    int lane = threadIdx.x & 31, w = threadIdx.x >> 5, nw = blockDim.x >> 5;
#pragma unroll
    for (int o = 1; o < 32; o <<= 1) { int u = __shfl_up_sync(full, v, o); if (lane >= o) v += u; }
    if (lane == 31) warp_sums[w] = v;
    __syncthreads();
    if (w == 0) {
        int s = (lane < nw) ? warp_sums[lane] : 0;
#pragma unroll
        for (int o = 1; o < 32; o <<= 1) { int u = __shfl_up_sync(full, s, o); if (lane >= o) s += u; }
        if (lane < nw) warp_sums[lane] = s;
    }
    __syncthreads();
    if (w > 0) v += warp_sums[w - 1];
    return v;
}
__global__ void scan_phase1_kernel() {
    __shared__ int ws[32];
    int gid = blockIdx.x * 1024 + threadIdx.x;
    int incl = block_incl_scan(g_indeg[gid], ws);
    g_scan[gid] = incl;
    if (threadIdx.x == 1023) g_bsum[blockIdx.x] = incl;
}
__global__ void scan_phase2_kernel() {
    __shared__ int ws[32];
    int v = g_bsum[threadIdx.x];
    int incl = block_incl_scan(v, ws);
    g_bsum[threadIdx.x] = incl - v;
}
__global__ void scan_phase3_kernel() {
    int gid = blockIdx.x * blockDim.x + threadIdx.x;
    if (gid < NN) {
        g_rowptr[gid + 1] = g_scan[gid] + g_bsum[gid >> 10];
        if (gid == 0) g_rowptr[0] = 0;
    }
}
__global__ void selfloop_init_kernel() {
    int i = blockIdx.x * blockDim.x + threadIdx.x;
    if (i < NN) { int p = g_rowptr[i]; g_csrc[p] = i; g_cursor[i] = p + 1; }
}
__global__ void scatter_edges_kernel(const int* __restrict__ ei) {
    int e = blockIdx.x * blockDim.x + threadIdx.x;
    if (e < EE) { int p = atomicAdd(&g_cursor[ei[EE + e]], 1); g_csrc[p] = ei[e]; }
}

// ---------------- fp32 -> fp16 conversion pass ----------------
__global__ void conv_half_kernel(const float4* __restrict__ in, __half2* __restrict__ out) {
    int i = blockIdx.x * blockDim.x + threadIdx.x;
    float4 v = in[i];
    out[2 * i]     = __floats2half2_rn(v.x, v.y);
    out[2 * i + 1] = __floats2half2_rn(v.z, v.w);
}

// ---------------- transpose 768x768 -> fp16 K-major ----------------
__global__ void transpose768_kernel(const float* __restrict__ W, __half* __restrict__ WT) {
    __shared__ float t[32][33];
    int bx = blockIdx.x * 32, by = blockIdx.y * 32;
    for (int i = threadIdx.y; i < 32; i += 8)
        t[i][threadIdx.x] = W[(size_t)(by + i) * D + bx + threadIdx.x];
    __syncthreads();
    for (int i = threadIdx.y; i < 32; i += 8)
        WT[(size_t)(bx + i) * D + by + threadIdx.x] = __float2half_rn(t[threadIdx.x][i]);
}

// ---------------- fp16 mma GEMM + fused attention-score epilogue ----------------
constexpr int BK   = 64;
constexpr int KSTG = D / BK;                      // 12
constexpr int RS   = 72;
constexpr int TILE_H  = 128 * RS;
constexpr int STAGE_H = 2 * TILE_H;
constexpr int SM_GEMM = 3 * STAGE_H * 2;          // 110,592 bytes

__global__ __launch_bounds__(256, 2) void mma_gemm_kernel(
    const __half* __restrict__ A, const __half* __restrict__ BT,
    float* __restrict__ Cf, __half* __restrict__ Ch, const float* __restrict__ bias,
    const float* __restrict__ att_s, const float* __restrict__ att_d,
    float* __restrict__ asrc, float* __restrict__ adst)
{
    extern __shared__ __half smh[];
    const int tid  = threadIdx.x;
    const int wid  = tid >> 5, lane = tid & 31;
    const int gid  = lane >> 2, tig = lane & 3;
    const int m0   = blockIdx.y * 128;
    const int n0   = blockIdx.x * 128;
    const int wm   = (wid & 1) * 64;
    const int wn   = (wid >> 1) * 32;

    const __half* ga = A  + (size_t)m0 * D;
    const __half* gb = BT + (size_t)n0 * D;
    const uint32_t sm_u = smem_u32(smh);

    auto load_stage = [&](int buf, int ks) {
        int k0 = ks * BK;
        uint32_t abase = sm_u + (uint32_t)buf * STAGE_H * 2;
        uint32_t bbase = abase + TILE_H * 2;
#pragma unroll
        for (int t = tid; t < 1024; t += 256) {
            int row = t >> 3, c = t & 7;
            uint32_t off = (uint32_t)(row * RS + c * 8) * 2;
            cp16(abase + off, ga + (size_t)row * D + k0 + c * 8);
            cp16(bbase + off, gb + (size_t)row * D + k0 + c * 8);
        }
        CP_COMMIT();
    };

    float acc[4][4][4];
#pragma unroll
    for (int i = 0; i < 4; i++)
#pragma unroll
        for (int j = 0; j < 4; j++)
#pragma unroll
            for (int q = 0; q < 4; q++) acc[i][j][q] = 0.0f;

    load_stage(0, 0);
    load_stage(1, 1);

    for (int s = 0; s < KSTG; ++s) {
        int buf = s % 3;
        if (s < KSTG - 1) CP_WAIT(1); else CP_WAIT(0);
        __syncthreads();

        const __half* Ab = smh + buf * STAGE_H + (wm + gid) * RS;
        const __half* Bb = smh + buf * STAGE_H + TILE_H + (wn + gid) * RS;
#pragma unroll
        for (int kk = 0; kk < 4; ++kk) {
            uint32_t af[4][4], bf[4][2];
#pragma unroll
            for (int i = 0; i < 4; ++i) {
                const __half* p = Ab + i * (16 * RS) + kk * 16 + tig * 2;
                af[i][0] = *(const uint32_t*)(p);
                af[i][1] = *(const uint32_t*)(p + 8 * RS);
                af[i][2] = *(const uint32_t*)(p + 8);
                af[i][3] = *(const uint32_t*)(p + 8 * RS + 8);
            }
#pragma unroll
            for (int j = 0; j < 4; ++j) {
                const __half* p = Bb + j * (8 * RS) + kk * 16 + tig * 2;
                bf[j][0] = *(const uint32_t*)(p);
                bf[j][1] = *(const uint32_t*)(p + 8);
            }
#pragma unroll
            for (int i = 0; i < 4; ++i)
#pragma unroll
                for (int j = 0; j < 4; ++j)
                    mma16(acc[i][j], af[i], bf[j]);
        }
        if (s + 2 < KSTG) load_stage((s + 2) % 3, s + 2);
    }

    if (att_s) {
        const unsigned full = 0xffffffffu;
        const int h = (n0 + wn) / HD;
        float asv[8], adv[8];
#pragma unroll
        for (int j = 0; j < 4; ++j) {
            int cb = n0 + wn + j * 8 + tig * 2;
            asv[j * 2 + 0] = att_s[cb];     asv[j * 2 + 1] = att_s[cb + 1];
            adv[j * 2 + 0] = att_d[cb];     adv[j * 2 + 1] = att_d[cb + 1];
        }
        float ps[8], pd[8];
#pragma unroll
        for (int i = 0; i < 4; ++i) {
            float s0 = 0, s1 = 0, d0 = 0, d1 = 0;
#pragma unroll
            for (int j = 0; j < 4; ++j) {
                s0 += acc[i][j][0] * asv[j * 2] + acc[i][j][1] * asv[j * 2 + 1];
                s1 += acc[i][j][2] * asv[j * 2] + acc[i][j][3] * asv[j * 2 + 1];
                d0 += acc[i][j][0] * adv[j * 2] + acc[i][j][1] * adv[j * 2 + 1];
                d1 += acc[i][j][2] * adv[j * 2] + acc[i][j][3] * adv[j * 2 + 1];
            }
            ps[i * 2] = s0; ps[i * 2 + 1] = s1; pd[i * 2] = d0; pd[i * 2 + 1] = d1;
        }
#pragma unroll
        for (int o = 1; o <= 2; o <<= 1)
#pragma unroll
            for (int k = 0; k < 8; ++k) {
                ps[k] += __shfl_xor_sync(full, ps[k], o);
                pd[k] += __shfl_xor_sync(full, pd[k], o);
            }
        if (tig == 0) {
#pragma unroll
            for (int i = 0; i < 4; ++i) {
                int r0 = m0 + wm + i * 16 + gid;
                atomicAdd(&asrc[r0 * HH + h],       ps[i * 2]);
                atomicAdd(&asrc[(r0 + 8) * HH + h], ps[i * 2 + 1]);
                atomicAdd(&adst[r0 * HH + h],       pd[i * 2]);
                atomicAdd(&adst[(r0 + 8) * HH + h], pd[i * 2 + 1]);
            }
        }
    }

    if (Ch) {
#pragma unroll
        for (int i = 0; i < 4; ++i) {
            int r = m0 + wm + i * 16 + gid;
#pragma unroll
            for (int j = 0; j < 4; ++j) {
                int cb = n0 + wn + j * 8 + tig * 2;
                *(__half2*)&Ch[(size_t)r * D + cb]       = __floats2half2_rn(acc[i][j][0], acc[i][j][1]);
                *(__half2*)&Ch[(size_t)(r + 8) * D + cb] = __floats2half2_rn(acc[i][j][2], acc[i][j][3]);
            }
        }
    } else {
#pragma unroll
        for (int i = 0; i < 4; ++i) {
            int r = m0 + wm + i * 16 + gid;
#pragma unroll
            for (int j = 0; j < 4; ++j) {
                int cb = n0 + wn + j * 8 + tig * 2;
                float bx = bias ? bias[cb] : 0.0f, by = bias ? bias[cb + 1] : 0.0f;
                float2 v0 = { acc[i][j][0] + bx, acc[i][j][1] + by };
                float2 v1 = { acc[i][j][2] + bx, acc[i][j][3] + by };
                *(float2*)&Cf[(size_t)r * D + cb]       = v0;
                *(float2*)&Cf[(size_t)(r + 8) * D + cb] = v1;
            }
        }
    }
}

__device__ __forceinline__ float leaky02(float e) { return e > 0.0f ? e : 0.2f * e; }

// ---------------- plain GAT node compute (R10 version — used by fused l2+pool) ----------
__device__ __forceinline__ void gat_node_compute(
    int n, int lane,
    const float* __restrict__ bias, const float* __restrict__ gamma,
    const float* __restrict__ beta, const __half* h_res, float out[3][8])
{
    const unsigned full = 0xffffffffu;
    int beg = g_rowptr[n], end = g_rowptr[n + 1];

    float ad0 = g_adst[n * 4 + 0], ad1 = g_adst[n * 4 + 1];
    float ad2 = g_adst[n * 4 + 2], ad3 = g_adst[n * 4 + 3];

    float m0 = -1e30f, m1 = -1e30f, m2 = -1e30f, m3 = -1e30f;
    for (int p = beg + lane; p < end; p += 32) {
        int s = g_csrc[p];
        m0 = fmaxf(m0, leaky02(g_asrc[s * 4 + 0] + ad0));
        m1 = fmaxf(m1, leaky02(g_asrc[s * 4 + 1] + ad1));
        m2 = fmaxf(m2, leaky02(g_asrc[s * 4 + 2] + ad2));
        m3 = fmaxf(m3, leaky02(g_asrc[s * 4 + 3] + ad3));
    }
#pragma unroll
    for (int o = 16; o; o >>= 1) {
        m0 = fmaxf(m0, __shfl_xor_sync(full, m0, o));
        m1 = fmaxf(m1, __shfl_xor_sync(full, m1, o));
        m2 = fmaxf(m2, __shfl_xor_sync(full, m2, o));
        m3 = fmaxf(m3, __shfl_xor_sync(full, m3, o));
    }

    float d0 = 0, d1 = 0, d2 = 0, d3 = 0;
    for (int p = beg + lane; p < end; p += 32) {
        int s = g_csrc[p];
        d0 += __expf(leaky02(g_asrc[s * 4 + 0] + ad0) - m0);
        d1 += __expf(leaky02(g_asrc[s * 4 + 1] + ad1) - m1);
        d2 += __expf(leaky02(g_asrc[s * 4 + 2] + ad2) - m2);
        d3 += __expf(leaky02(g_asrc[s * 4 + 3] + ad3) - m3);
    }
#pragma unroll
    for (int o = 16; o; o >>= 1) {
        d0 += __shfl_xor_sync(full, d0, o);
        d1 += __shfl_xor_sync(full, d1, o);
        d2 += __shfl_xor_sync(full, d2, o);
        d3 += __shfl_xor_sync(full, d3, o);
    }
    float i0 = 1.0f / d0, i1 = 1.0f / d1, i2 = 1.0f / d2, i3 = 1.0f / d3;

    float acc[3][8];
#pragma unroll
    for (int i = 0; i < 3; i++)
#pragma unroll
        for (int k = 0; k < 8; k++) acc[i][k] = 0.0f;

    for (int p = beg; p < end; ++p) {
        int s = g_csrc[p];
        float a0 = __expf(leaky02(g_asrc[s * 4 + 0] + ad0) - m0) * i0;
        float a1 = __expf(leaky02(g_asrc[s * 4 + 1] + ad1) - m1) * i1;
        float a2 = __expf(leaky02(g_asrc[s * 4 + 2] + ad2) - m2) * i2;
        float a3 = __expf(leaky02(g_asrc[s * 4 + 3] + ad3) - m3) * i3;
        const uint4* row = (const uint4*)(g_xwh + (size_t)s * D);
#pragma unroll
        for (int i = 0; i < 3; i++) {
            int idx = i * 256 + lane * 8;
            int h = idx / HD;
            float a = (h == 0) ? a0 : (h == 1) ? a1 : (h == 2) ? a2 : a3;
            uint4 v = __ldg(&row[i * 32 + lane]);
            float2 f0 = __half22float2(*(__half2*)&v.x);
            float2 f1 = __half22float2(*(__half2*)&v.y);
            float2 f2 = __half22float2(*(__half2*)&v.z);
            float2 f3 = __half22float2(*(__half2*)&v.w);
            acc[i][0] = fmaf(a, f0.x, acc[i][0]);
            acc[i][1] = fmaf(a, f0.y, acc[i][1]);
            acc[i][2] = fmaf(a, f1.x, acc[i][2]);
            acc[i][3] = fmaf(a, f1.y, acc[i][3]);
            acc[i][4] = fmaf(a, f2.x, acc[i][4]);
            acc[i][5] = fmaf(a, f2.y, acc[i][5]);
            acc[i][6] = fmaf(a, f3.x, acc[i][6]);
            acc[i][7] = fmaf(a, f3.y, acc[i][7]);
        }
    }

    float s1 = 0.0f;
#pragma unroll
    for (int i = 0; i < 3; i++) {
        int idx = i * 256 + lane * 8;
        float4 b0 = *(const float4*)(bias + idx);
        float4 b1 = *(const float4*)(bias + idx + 4);
        acc[i][0] += b0.x; acc[i][1] += b0.y; acc[i][2] += b0.z; acc[i][3] += b0.w;
        acc[i][4] += b1.x; acc[i][5] += b1.y; acc[i][6] += b1.z; acc[i][7] += b1.w;
#pragma unroll
        for (int k = 0; k < 8; k++) s1 += acc[i][k];
    }
#pragma unroll
    for (int o = 16; o; o >>= 1) s1 += __shfl_xor_sync(full, s1, o);
    float mu = s1 * (1.0f / 768.0f);

    float s2 = 0.0f;
#pragma unroll
    for (int i = 0; i < 3; i++)
#pragma unroll
        for (int k = 0; k < 8; k++) { float dxv = acc[i][k] - mu; s2 += dxv * dxv; }
#pragma unroll
    for (int o = 16; o; o >>= 1) s2 += __shfl_xor_sync(full, s2, o);
    float rstd = rsqrtf(s2 * (1.0f / 768.0f) + 1e-5f);

#pragma unroll
    for (int i = 0; i < 3; i++) {
        int idx = i * 256 + lane * 8;
        float4 g0 = *(const float4*)(gamma + idx);
        float4 g1 = *(const float4*)(gamma + idx + 4);
        float4 e0 = *(const float4*)(beta + idx);
        float4 e1 = *(const float4*)(beta + idx + 4);
        uint4 rv = *(const uint4*)(h_res + (size_t)n * D + idx);
        float2 r0 = __half22float2(*(__half2*)&rv.x);
        float2 r1 = __half22float2(*(__half2*)&rv.y);
        float2 r2 = __half22float2(*(__half2*)&rv.z);
        float2 r3 = __half22float2(*(__half2*)&rv.w);
        out[i][0] = fmaxf(fmaf((acc[i][0] - mu) * rstd, g0.x, e0.x), 0.0f) + r0.x;
        out[i][1] = fmaxf(fmaf((acc[i][1] - mu) * rstd, g0.y, e0.y), 0.0f) + r0.y;
        out[i][2] = fmaxf(fmaf((acc[i][2] - mu) * rstd, g0.z, e0.z), 0.0f) + r1.x;
        out[i][3] = fmaxf(fmaf((acc[i][3] - mu) * rstd, g0.w, e0.w), 0.0f) + r1.y;
        out[i][4] = fmaxf(fmaf((acc[i][4] - mu) * rstd, g1.x, e1.x), 0.0f) + r2.x;
        out[i][5] = fmaxf(fmaf((acc[i][5] - mu) * rstd, g1.y, e1.y), 0.0f) + r2.y;
        out[i][6] = fmaxf(fmaf((acc[i][6] - mu) * rstd, g1.z, e1.z), 0.0f) + r3.x;
        out[i][7] = fmaxf(fmaf((acc[i][7] - mu) * rstd, g1.w, e1.w), 0.0f) + r3.y;
    }
}

// ---------------- layer 1: smem score cache + 1-deep prefetch (R11's kernel) ----------
__global__ __launch_bounds__(256) void gat_l1_kernel(
    const float* __restrict__ bias, const float* __restrict__ gamma,
    const float* __restrict__ beta, const __half* h_res, __half* h_out)
{
    __shared__ float ews_all[8 * 4 * MAXE];
    const unsigned full = 0xffffffffu;
    int wid  = threadIdx.x >> 5;
    int lane = threadIdx.x & 31;
    int n = blockIdx.x * 8 + wid;
    float* ews = &ews_all[wid * 4 * MAXE];

    int beg = g_rowptr[n], end = g_rowptr[n + 1];
    float4 ad = *(const float4*)&g_adst[n * 4];

    float m0 = -1e30f, m1 = -1e30f, m2 = -1e30f, m3 = -1e30f;
    for (int p = beg + lane; p < end; p += 32) {
        int s = g_csrc[p];
        float4 sv = *(const float4*)&g_asrc[s * 4];
        float e0 = leaky02(sv.x + ad.x), e1 = leaky02(sv.y + ad.y);
        float e2 = leaky02(sv.z + ad.z), e3 = leaky02(sv.w + ad.w);
        int e = p - beg;
        if (e < MAXE) {
            ews[e] = e0; ews[MAXE + e] = e1; ews[2 * MAXE + e] = e2; ews[3 * MAXE + e] = e3;
        }
        m0 = fmaxf(m0, e0); m1 = fmaxf(m1, e1); m2 = fmaxf(m2, e2); m3 = fmaxf(m3, e3);
    }
#pragma unroll
    for (int o = 16; o; o >>= 1) {
        m0 = fmaxf(m0, __shfl_xor_sync(full, m0, o));
        m1 = fmaxf(m1, __shfl_xor_sync(full, m1, o));
        m2 = fmaxf(m2, __shfl_xor_sync(full, m2, o));
        m3 = fmaxf(m3, __shfl_xor_sync(full, m3, o));
    }

    float d0 = 0, d1 = 0, d2 = 0, d3 = 0;
    for (int p = beg + lane; p < end; p += 32) {
        int e = p - beg;
        float e0, e1, e2, e3;
        if (e < MAXE) {
            e0 = ews[e]; e1 = ews[MAXE + e]; e2 = ews[2 * MAXE + e]; e3 = ews[3 * MAXE + e];
        } else {
            int s = g_csrc[p];
            float4 sv = *(const float4*)&g_asrc[s * 4];
            e0 = leaky02(sv.x + ad.x); e1 = leaky02(sv.y + ad.y);
            e2 = leaky02(sv.z + ad.z); e3 = leaky02(sv.w + ad.w);
        }
        float x0 = __expf(e0 - m0), x1 = __expf(e1 - m1);
        float x2 = __expf(e2 - m2), x3 = __expf(e3 - m3);
        if (e < MAXE) {
            ews[e] = x0; ews[MAXE + e] = x1; ews[2 * MAXE + e] = x2; ews[3 * MAXE + e] = x3;
        }
        d0 += x0; d1 += x1; d2 += x2; d3 += x3;
    }
#pragma unroll
    for (int o = 16; o; o >>= 1) {
        d0 += __shfl_xor_sync(full, d0, o);
        d1 += __shfl_xor_sync(full, d1, o);
        d2 += __shfl_xor_sync(full, d2, o);
        d3 += __shfl_xor_sync(full, d3, o);
    }
    float i0 = 1.0f / d0, i1 = 1.0f / d1, i2 = 1.0f / d2, i3 = 1.0f / d3;
    __syncwarp();

    float acc[3][8];
#pragma unroll
    for (int i = 0; i < 3; i++)
#pragma unroll
        for (int k = 0; k < 8; k++) acc[i][k] = 0.0f;

    const uint4* r0p = (const uint4*)(g_xwh + (size_t)g_csrc[beg] * D);
    uint4 f0 = __ldg(&r0p[lane]), f1 = __ldg(&r0p[32 + lane]), f2 = __ldg(&r0p[64 + lane]);

    for (int p = beg; p < end; ++p) {
        uint4 c0 = f0, c1 = f1, c2 = f2;
        int e = p - beg;
        float a0, a1, a2, a3;
        if (e < MAXE) {
            a0 = ews[e] * i0; a1 = ews[MAXE + e] * i1;
            a2 = ews[2 * MAXE + e] * i2; a3 = ews[3 * MAXE + e] * i3;
        } else {
            int s = g_csrc[p];
            float4 sv = *(const float4*)&g_asrc[s * 4];
            a0 = __expf(leaky02(sv.x + ad.x) - m0) * i0;
            a1 = __expf(leaky02(sv.y + ad.y) - m1) * i1;
            a2 = __expf(leaky02(sv.z + ad.z) - m2) * i2;
            a3 = __expf(leaky02(sv.w + ad.w) - m3) * i3;
        }
        if (p + 1 < end) {
            const uint4* rn = (const uint4*)(g_xwh + (size_t)g_csrc[p + 1] * D);
            f0 = __ldg(&rn[lane]); f1 = __ldg(&rn[32 + lane]); f2 = __ldg(&rn[64 + lane]);
        }
#pragma unroll
        for (int i = 0; i < 3; i++) {
            int idx = i * 256 + lane * 8;
            int h = idx / HD;
            float a = (h == 0) ? a0 : (h == 1) ? a1 : (h == 2) ? a2 : a3;
            uint4 v = (i == 0) ? c0 : (i == 1) ? c1 : c2;
            float2 q0 = __half22float2(*(__half2*)&v.x);
            float2 q1 = __half22float2(*(__half2*)&v.y);
            float2 q2 = __half22float2(*(__half2*)&v.z);
            float2 q3 = __half22float2(*(__half2*)&v.w);
            acc[i][0] = fmaf(a, q0.x, acc[i][0]);
            acc[i][1] = fmaf(a, q0.y, acc[i][1]);
            acc[i][2] = fmaf(a, q1.x, acc[i][2]);
            acc[i][3] = fmaf(a, q1.y, acc[i][3]);
            acc[i][4] = fmaf(a, q2.x, acc[i][4]);
            acc[i][5] = fmaf(a, q2.y, acc[i][5]);
            acc[i][6] = fmaf(a, q3.x, acc[i][6]);
            acc[i][7] = fmaf(a, q3.y, acc[i][7]);
        }
    }

    float s1 = 0.0f;
#pragma unroll
    for (int i = 0; i < 3; i++) {
        int idx = i * 256 + lane * 8;
        float4 b0 = *(const float4*)(bias + idx);
        float4 b1 = *(const float4*)(bias + idx + 4);
        acc[i][0] += b0.x; acc[i][1] += b0.y; acc[i][2] += b0.z; acc[i][3] += b0.w;
        acc[i][4] += b1.x; acc[i][5] += b1.y; acc[i][6] += b1.z; acc[i][7] += b1.w;
#pragma unroll
        for (int k = 0; k < 8; k++) s1 += acc[i][k];
    }
#pragma unroll
    for (int o = 16; o; o >>= 1) s1 += __shfl_xor_sync(full, s1, o);
    float mu = s1 * (1.0f / 768.0f);

    float s2 = 0.0f;
#pragma unroll
    for (int i = 0; i < 3; i++)
#pragma unroll
        for (int k = 0; k < 8; k++) { float dv = acc[i][k] - mu; s2 += dv * dv; }
#pragma unroll
    for (int o = 16; o; o >>= 1) s2 += __shfl_xor_sync(full, s2, o);
    float rstd = rsqrtf(s2 * (1.0f / 768.0f) + 1e-5f);

#pragma unroll
    for (int i = 0; i < 3; i++) {
        int idx = i * 256 + lane * 8;
        float4 g0 = *(const float4*)(gamma + idx);
        float4 g1 = *(const float4*)(gamma + idx + 4);
        float4 e0 = *(const float4*)(beta + idx);
        float4 e1 = *(const float4*)(beta + idx + 4);
        uint4 rv = *(const uint4*)(h_res + (size_t)n * D + idx);
        float2 r0 = __half22float2(*(__half2*)&rv.x);
        float2 r1 = __half22float2(*(__half2*)&rv.y);
        float2 r2 = __half22float2(*(__half2*)&rv.z);
        float2 r3 = __half22float2(*(__half2*)&rv.w);
        float o0 = fmaxf(fmaf((acc[i][0] - mu) * rstd, g0.x, e0.x), 0.0f) + r0.x;
        float o1 = fmaxf(fmaf((acc[i][1] - mu) * rstd, g0.y, e0.y), 0.0f) + r0.y;
        float o2 = fmaxf(fmaf((acc[i][2] - mu) * rstd, g0.z, e0.z), 0.0f) + r1.x;
        float o3 = fmaxf(fmaf((acc[i][3] - mu) * rstd, g0.w, e0.w), 0.0f) + r1.y;
        float o4 = fmaxf(fmaf((acc[i][4] - mu) * rstd, g1.x, e1.x), 0.0f) + r2.x;
        float o5 = fmaxf(fmaf((acc[i][5] - mu) * rstd, g1.y, e1.y), 0.0f) + r2.y;
        float o6 = fmaxf(fmaf((acc[i][6] - mu) * rstd, g1.z, e1.z), 0.0f) + r3.x;
        float o7 = fmaxf(fmaf((acc[i][7] - mu) * rstd, g1.w, e1.w), 0.0f) + r3.y;
        uint4 hv;
        *(__half2*)&hv.x = __floats2half2_rn(o0, o1);
        *(__half2*)&hv.y = __floats2half2_rn(o2, o3);
        *(__half2*)&hv.z = __floats2half2_rn(o4, o5);
        *(__half2*)&hv.w = __floats2half2_rn(o6, o7);
        *(uint4*)(h_out + (size_t)n * D + idx) = hv;
    }
}

// ---------------- layer 2 + pooling fused (R10's kernel) ----------------
__global__ __launch_bounds__(1024) void gat_l2_pool_kernel(
    const float* __restrict__ bias, const float* __restrict__ gamma,
    const float* __restrict__ beta, const __half* h_res, __half* pool_out)
{
    extern __shared__ float psm[];        // [32][768]
    int wid  = threadIdx.x >> 5;
    int lane = threadIdx.x & 31;
    int n = blockIdx.x * 32 + wid;
    float out[3][8];
    gat_node_compute(n, lane, bias, gamma, beta, h_res, out);
#pragma unroll
    for (int i = 0; i < 3; i++) {
        int idx = i * 256 + lane * 8;
        *(float4*)&psm[wid * D + idx]     = make_float4(out[i][0], out[i][1], out[i][2], out[i][3]);
        *(float4*)&psm[wid * D + idx + 4] = make_float4(out[i][4], out[i][5], out[i][6], out[i][7]);
    }
    __syncthreads();
    if (threadIdx.x < D) {
        float s = 0.0f;
#pragma unroll
        for (int r = 0; r < 32; r++) s += psm[r * D + threadIdx.x];
        pool_out[(size_t)blockIdx.x * D + threadIdx.x] = __float2half_rn(s * (1.0f / 32.0f));
    }
}

// ---------------- launcher ----------------
extern "C" void kernel_launch(void* const* d_in, const int* in_sizes, int n_in,
                              void* d_out, int out_size)
{
    const float* x   = (const float*)d_in[0];
    const int*   ei  = (const int*)d_in[1];
    const float* W1  = (const float*)d_in[3];
    const float* as1 = (const float*)d_in[4];
    const float* ad1 = (const float*)d_in[5];
    const float* b1  = (const float*)d_in[6];
    const float* g1  = (const float*)d_in[7];
    const float* be1 = (const float*)d_in[8];
    const float* W2  = (const float*)d_in[9];
    const float* as2 = (const float*)d_in[10];
    const float* ad2 = (const float*)d_in[11];
    const float* b2  = (const float*)d_in[12];
    const float* g2  = (const float*)d_in[13];
    const float* be2 = (const float*)d_in[14];
    const float* Wo  = (const float*)d_in[15];
    const float* bo  = (const float*)d_in[16];
    float* out = (float*)d_out;

    float *p_as, *p_ad;
    __half *p_xh, *p_xwh, *p_wth, *p_hgh;
    cudaGetSymbolAddress((void**)&p_xh,  g_xh);
    cudaGetSymbolAddress((void**)&p_xwh, g_xwh);
    cudaGetSymbolAddress((void**)&p_wth, g_wth);
    cudaGetSymbolAddress((void**)&p_hgh, g_hgh);
    cudaGetSymbolAddress((void**)&p_as,  g_asrc);
    cudaGetSymbolAddress((void**)&p_ad,  g_adst);

    cudaFuncSetAttribute(mma_gemm_kernel,
                         cudaFuncAttributeMaxDynamicSharedMemorySize, SM_GEMM);
    cudaFuncSetAttribute(gat_l2_pool_kernel,
                         cudaFuncAttributeMaxDynamicSharedMemorySize, 32 * D * 4);

    dim3 tgrid(24, 24), tblk(32, 8);
    dim3 ggrid(D / 128, NN / 128);     // (6, 1024)

    conv_half_kernel<<<(NN * (D / 4)) / 256, 256>>>((const float4*)x, (__half2*)p_xh); // 0
    transpose768_kernel<<<tgrid, tblk>>>(W1, p_wth);                                    // 1
    init_deg_kernel<<<NN / 256, 256>>>();                                               // 2
    mma_gemm_kernel<<<ggrid, 256, SM_GEMM>>>(p_xh, p_wth, nullptr, p_xwh, nullptr,      // 3
                                             as1, ad1, p_as, p_ad);
    count_deg_kernel<<<EE / 256, 256>>>(ei);
    scan_phase1_kernel<<<NN / 1024, 1024>>>();
    scan_phase2_kernel<<<1, 128>>>();
    scan_phase3_kernel<<<(NN + 255) / 256, 256>>>();
    selfloop_init_kernel<<<NN / 256, 256>>>();
    scatter_edges_kernel<<<EE / 256, 256>>>(ei);

    // layer 1: residual fp16 x (in g_xh), write h1 fp16 IN PLACE into g_xh
    gat_l1_kernel<<<NN / 8, 256>>>(b1, g1, be1, p_xh, p_xh);

    // layer 2
    zero_attn_kernel<<<(NN * HH) / 256, 256>>>();
    transpose768_kernel<<<tgrid, tblk>>>(W2, p_wth);
    mma_gemm_kernel<<<ggrid, 256, SM_GEMM>>>(p_xh, p_wth, nullptr, p_xwh, nullptr,
                                             as2, ad2, p_as, p_ad);
    // layer 2 GAT + pooling fused: one graph per 1024-thread block
    gat_l2_pool_kernel<<<GG, 1024, 32 * D * 4>>>(b2, g2, be2, p_xh, p_hgh);

    // output projection (fp32 out + bias)
    transpose768_kernel<<<tgrid, tblk>>>(Wo, p_wth);
    mma_gemm_kernel<<<dim3(D / 128, GG / 128), 256, SM_GEMM>>>(p_hgh, p_wth, out, nullptr, bo,
                                                               nullptr, nullptr, nullptr, nullptr);
}

// round 14
// speedup vs baseline: 1.1385x; 1.0065x over previous
#include <cuda_runtime.h>
#include <cuda_fp16.h>
#include <cstdint>

// ---------------- problem constants ----------------
constexpr int NN = 131072;
constexpr int EE = 262144;
constexpr int GG = 4096;
constexpr int D  = 768;
constexpr int HH = 4;
constexpr int HD = 192;
constexpr int ET = EE + NN;
constexpr int MAXE = 32;

// ---------------- scratch (device globals) ----------------
__device__ __align__(256) __half g_xh[(size_t)NN * D];   // fp16: x, then h1 (in-place)
__device__ __align__(256) __half g_xwh[(size_t)NN * D];  // x @ W (fp16)
__device__ __align__(256) __half g_wth[D * D];           // W^T (K-major, fp16)
__device__ __align__(256) __half g_hgh[GG * D];          // pooled (fp16)
__device__ float g_asrc[NN * HH];
__device__ float g_adst[NN * HH];
__device__ int   g_indeg[NN];
__device__ int   g_cursor[NN];
__device__ int   g_rowptr[NN + 1];
__device__ int   g_scan[NN];
__device__ int   g_bsum[256];
__device__ int   g_csrc[ET];

// ---------------- helpers ----------------
__device__ __forceinline__ void cp16(uint32_t saddr, const void* g) {
    asm volatile("cp.async.cg.shared.global [%0], [%1], 16;" :: "r"(saddr), "l"(g));
}
__device__ __forceinline__ uint32_t smem_u32(const void* p) {
    uint32_t a;
    asm("{ .reg .u64 t; cvta.to.shared.u64 t, %1; cvt.u32.u64 %0, t; }" : "=r"(a) : "l"(p));
    return a;
}
#define CP_COMMIT()  asm volatile("cp.async.commit_group;" ::: "memory")
#define CP_WAIT(n)   asm volatile("cp.async.wait_group %0;" :: "n"(n) : "memory")

__device__ __forceinline__ void mma16(float* d, const uint32_t* a, const uint32_t* b) {
    asm volatile(
        "mma.sync.aligned.m16n8k16.row.col.f32.f16.f16.f32 "
        "{%0,%1,%2,%3}, {%4,%5,%6,%7}, {%8,%9}, {%0,%1,%2,%3};"
        : "+f"(d[0]), "+f"(d[1]), "+f"(d[2]), "+f"(d[3])
        : "r"(a[0]), "r"(a[1]), "r"(a[2]), "r"(a[3]), "r"(b[0]), "r"(b[1]));
}

// ---------------- CSR construction ----------------
__global__ void init_deg_kernel() {
    int i = blockIdx.x * blockDim.x + threadIdx.x;
    if (i < NN) {
        g_indeg[i] = 1;
#pragma unroll
        for (int h = 0; h < HH; h++) { g_asrc[i * HH + h] = 0.0f; g_adst[i * HH + h] = 0.0f; }
    }
}
__global__ void zero_attn_kernel() {
    int i = blockIdx.x * blockDim.x + threadIdx.x;
    if (i < NN * HH) { g_asrc[i] = 0.0f; g_adst[i] = 0.0f; }
}
__global__ void count_deg_kernel(const int* __restrict__ ei) {
    int e = blockIdx.x * blockDim.x + threadIdx.x;
    if (e < EE) atomicAdd(&g_indeg[ei[EE + e]], 1);
}
__device__ __forceinline__ int block_incl_scan(int v, int* warp_sums) {
    const unsigned full = 0xffffffffu;
    int lane = threadIdx.x & 31, w = threadIdx.x >> 5, nw = blockDim.x >> 5;
#pragma unroll
    for (int o = 1; o < 32; o <<= 1) { int u = __shfl_up_sync(full, v, o); if (lane >= o) v += u; }
    if (lane == 31) warp_sums[w] = v;
    __syncthreads();
    if (w == 0) {
        int s = (lane < nw) ? warp_sums[lane] : 0;
#pragma unroll
        for (int o = 1; o < 32; o <<= 1) { int u = __shfl_up_sync(full, s, o); if (lane >= o) s += u; }
        if (lane < nw) warp_sums[lane] = s;
    }
    __syncthreads();
    if (w > 0) v += warp_sums[w - 1];
    return v;
}
__global__ void scan_phase1_kernel() {
    __shared__ int ws[32];
    int gid = blockIdx.x * 1024 + threadIdx.x;
    int incl = block_incl_scan(g_indeg[gid], ws);
    g_scan[gid] = incl;
    if (threadIdx.x == 1023) g_bsum[blockIdx.x] = incl;
}
__global__ void scan_phase2_kernel() {
    __shared__ int ws[32];
    int v = g_bsum[threadIdx.x];
    int incl = block_incl_scan(v, ws);
    g_bsum[threadIdx.x] = incl - v;
}
__global__ void scan_phase3_kernel() {
    int gid = blockIdx.x * blockDim.x + threadIdx.x;
    if (gid < NN) {
        g_rowptr[gid + 1] = g_scan[gid] + g_bsum[gid >> 10];
        if (gid == 0) g_rowptr[0] = 0;
    }
}
__global__ void selfloop_init_kernel() {
    int i = blockIdx.x * blockDim.x + threadIdx.x;
    if (i < NN) { int p = g_rowptr[i]; g_csrc[p] = i; g_cursor[i] = p + 1; }
}
__global__ void scatter_edges_kernel(const int* __restrict__ ei) {
    int e = blockIdx.x * blockDim.x + threadIdx.x;
    if (e < EE) { int p = atomicAdd(&g_cursor[ei[EE + e]], 1); g_csrc[p] = ei[e]; }
}

// ---------------- fp32 -> fp16 conversion pass ----------------
__global__ void conv_half_kernel(const float4* __restrict__ in, __half2* __restrict__ out) {
    int i = blockIdx.x * blockDim.x + threadIdx.x;
    float4 v = in[i];
    out[2 * i]     = __floats2half2_rn(v.x, v.y);
    out[2 * i + 1] = __floats2half2_rn(v.z, v.w);
}

// ---------------- transpose 768x768 -> fp16 K-major ----------------
__global__ void transpose768_kernel(const float* __restrict__ W, __half* __restrict__ WT) {
    __shared__ float t[32][33];
    int bx = blockIdx.x * 32, by = blockIdx.y * 32;
    for (int i = threadIdx.y; i < 32; i += 8)
        t[i][threadIdx.x] = W[(size_t)(by + i) * D + bx + threadIdx.x];
    __syncthreads();
    for (int i = threadIdx.y; i < 32; i += 8)
        WT[(size_t)(bx + i) * D + by + threadIdx.x] = __float2half_rn(t[threadIdx.x][i]);
}

// ---------------- fp16 mma GEMM + fused attention-score epilogue ----------------
constexpr int BK   = 64;
constexpr int KSTG = D / BK;                      // 12
constexpr int RS   = 72;
constexpr int TILE_H  = 128 * RS;
constexpr int STAGE_H = 2 * TILE_H;
constexpr int SM_GEMM = 3 * STAGE_H * 2;          // 110,592 bytes

__global__ __launch_bounds__(256, 2) void mma_gemm_kernel(
    const __half* __restrict__ A, const __half* __restrict__ BT,
    float* __restrict__ Cf, __half* __restrict__ Ch, const float* __restrict__ bias,
    const float* __restrict__ att_s, const float* __restrict__ att_d,
    float* __restrict__ asrc, float* __restrict__ adst)
{
    extern __shared__ __half smh[];
    const int tid  = threadIdx.x;
    const int wid  = tid >> 5, lane = tid & 31;
    const int gid  = lane >> 2, tig = lane & 3;
    const int m0   = blockIdx.y * 128;
    const int n0   = blockIdx.x * 128;
    const int wm   = (wid & 1) * 64;
    const int wn   = (wid >> 1) * 32;

    const __half* ga = A  + (size_t)m0 * D;
    const __half* gb = BT + (size_t)n0 * D;
    const uint32_t sm_u = smem_u32(smh);

    auto load_stage = [&](int buf, int ks) {
        int k0 = ks * BK;
        uint32_t abase = sm_u + (uint32_t)buf * STAGE_H * 2;
        uint32_t bbase = abase + TILE_H * 2;
#pragma unroll
        for (int t = tid; t < 1024; t += 256) {
            int row = t >> 3, c = t & 7;
            uint32_t off = (uint32_t)(row * RS + c * 8) * 2;
            cp16(abase + off, ga + (size_t)row * D + k0 + c * 8);
            cp16(bbase + off, gb + (size_t)row * D + k0 + c * 8);
        }
        CP_COMMIT();
    };

    float acc[4][4][4];
#pragma unroll
    for (int i = 0; i < 4; i++)
#pragma unroll
        for (int j = 0; j < 4; j++)
#pragma unroll
            for (int q = 0; q < 4; q++) acc[i][j][q] = 0.0f;

    load_stage(0, 0);
    load_stage(1, 1);

    for (int s = 0; s < KSTG; ++s) {
        int buf = s % 3;
        if (s < KSTG - 1) CP_WAIT(1); else CP_WAIT(0);
        __syncthreads();

        const __half* Ab = smh + buf * STAGE_H + (wm + gid) * RS;
        const __half* Bb = smh + buf * STAGE_H + TILE_H + (wn + gid) * RS;
#pragma unroll
        for (int kk = 0; kk < 4; ++kk) {
            uint32_t af[4][4], bf[4][2];
#pragma unroll
            for (int i = 0; i < 4; ++i) {
                const __half* p = Ab + i * (16 * RS) + kk * 16 + tig * 2;
                af[i][0] = *(const uint32_t*)(p);
                af[i][1] = *(const uint32_t*)(p + 8 * RS);
                af[i][2] = *(const uint32_t*)(p + 8);
                af[i][3] = *(const uint32_t*)(p + 8 * RS + 8);
            }
#pragma unroll
            for (int j = 0; j < 4; ++j) {
                const __half* p = Bb + j * (8 * RS) + kk * 16 + tig * 2;
                bf[j][0] = *(const uint32_t*)(p);
                bf[j][1] = *(const uint32_t*)(p + 8);
            }
#pragma unroll
            for (int i = 0; i < 4; ++i)
#pragma unroll
                for (int j = 0; j < 4; ++j)
                    mma16(acc[i][j], af[i], bf[j]);
        }
        if (s + 2 < KSTG) load_stage((s + 2) % 3, s + 2);
    }

    if (att_s) {
        const unsigned full = 0xffffffffu;
        const int h = (n0 + wn) / HD;
        float asv[8], adv[8];
#pragma unroll
        for (int j = 0; j < 4; ++j) {
            int cb = n0 + wn + j * 8 + tig * 2;
            asv[j * 2 + 0] = att_s[cb];     asv[j * 2 + 1] = att_s[cb + 1];
            adv[j * 2 + 0] = att_d[cb];     adv[j * 2 + 1] = att_d[cb + 1];
        }
        float ps[8], pd[8];
#pragma unroll
        for (int i = 0; i < 4; ++i) {
            float s0 = 0, s1 = 0, d0 = 0, d1 = 0;
#pragma unroll
            for (int j = 0; j < 4; ++j) {
                s0 += acc[i][j][0] * asv[j * 2] + acc[i][j][1] * asv[j * 2 + 1];
                s1 += acc[i][j][2] * asv[j * 2] + acc[i][j][3] * asv[j * 2 + 1];
                d0 += acc[i][j][0] * adv[j * 2] + acc[i][j][1] * adv[j * 2 + 1];
                d1 += acc[i][j][2] * adv[j * 2] + acc[i][j][3] * adv[j * 2 + 1];
            }
            ps[i * 2] = s0; ps[i * 2 + 1] = s1; pd[i * 2] = d0; pd[i * 2 + 1] = d1;
        }
#pragma unroll
        for (int o = 1; o <= 2; o <<= 1)
#pragma unroll
            for (int k = 0; k < 8; ++k) {
                ps[k] += __shfl_xor_sync(full, ps[k], o);
                pd[k] += __shfl_xor_sync(full, pd[k], o);
            }
        if (tig == 0) {
#pragma unroll
            for (int i = 0; i < 4; ++i) {
                int r0 = m0 + wm + i * 16 + gid;
                atomicAdd(&asrc[r0 * HH + h],       ps[i * 2]);
                atomicAdd(&asrc[(r0 + 8) * HH + h], ps[i * 2 + 1]);
                atomicAdd(&adst[r0 * HH + h],       pd[i * 2]);
                atomicAdd(&adst[(r0 + 8) * HH + h], pd[i * 2 + 1]);
            }
        }
    }

    if (Ch) {
#pragma unroll
        for (int i = 0; i < 4; ++i) {
            int r = m0 + wm + i * 16 + gid;
#pragma unroll
            for (int j = 0; j < 4; ++j) {
                int cb = n0 + wn + j * 8 + tig * 2;
                *(__half2*)&Ch[(size_t)r * D + cb]       = __floats2half2_rn(acc[i][j][0], acc[i][j][1]);
                *(__half2*)&Ch[(size_t)(r + 8) * D + cb] = __floats2half2_rn(acc[i][j][2], acc[i][j][3]);
            }
        }
    } else {
#pragma unroll
        for (int i = 0; i < 4; ++i) {
            int r = m0 + wm + i * 16 + gid;
#pragma unroll
            for (int j = 0; j < 4; ++j) {
                int cb = n0 + wn + j * 8 + tig * 2;
                float bx = bias ? bias[cb] : 0.0f, by = bias ? bias[cb + 1] : 0.0f;
                float2 v0 = { acc[i][j][0] + bx, acc[i][j][1] + by };
                float2 v1 = { acc[i][j][2] + bx, acc[i][j][3] + by };
                *(float2*)&Cf[(size_t)r * D + cb]       = v0;
                *(float2*)&Cf[(size_t)(r + 8) * D + cb] = v1;
            }
        }
    }
}

__device__ __forceinline__ float leaky02(float e) { return e > 0.0f ? e : 0.2f * e; }

// ---------------- cached GAT node compute (score cache in smem strip ews[4*MAXE]) -------
// no register prefetch — safe for 1024-thread blocks (64-reg cap)
__device__ __forceinline__ void gat_node_compute_cached(
    int n, int lane, float* ews,
    const float* __restrict__ bias, const float* __restrict__ gamma,
    const float* __restrict__ beta, const __half* h_res, float out[3][8])
{
    const unsigned full = 0xffffffffu;
    int beg = g_rowptr[n], end = g_rowptr[n + 1];
    float4 ad = *(const float4*)&g_adst[n * 4];

    float m0 = -1e30f, m1 = -1e30f, m2 = -1e30f, m3 = -1e30f;
    for (int p = beg + lane; p < end; p += 32) {
        int s = g_csrc[p];
        float4 sv = *(const float4*)&g_asrc[s * 4];
        float e0 = leaky02(sv.x + ad.x), e1 = leaky02(sv.y + ad.y);
        float e2 = leaky02(sv.z + ad.z), e3 = leaky02(sv.w + ad.w);
        int e = p - beg;
        if (e < MAXE) {
            ews[e] = e0; ews[MAXE + e] = e1; ews[2 * MAXE + e] = e2; ews[3 * MAXE + e] = e3;
        }
        m0 = fmaxf(m0, e0); m1 = fmaxf(m1, e1); m2 = fmaxf(m2, e2); m3 = fmaxf(m3, e3);
    }
#pragma unroll
    for (int o = 16; o; o >>= 1) {
        m0 = fmaxf(m0, __shfl_xor_sync(full, m0, o));
        m1 = fmaxf(m1, __shfl_xor_sync(full, m1, o));
        m2 = fmaxf(m2, __shfl_xor_sync(full, m2, o));
        m3 = fmaxf(m3, __shfl_xor_sync(full, m3, o));
    }

    float d0 = 0, d1 = 0, d2 = 0, d3 = 0;
    for (int p = beg + lane; p < end; p += 32) {
        int e = p - beg;
        float e0, e1, e2, e3;
        if (e < MAXE) {
            e0 = ews[e]; e1 = ews[MAXE + e]; e2 = ews[2 * MAXE + e]; e3 = ews[3 * MAXE + e];
        } else {
            int s = g_csrc[p];
            float4 sv = *(const float4*)&g_asrc[s * 4];
            e0 = leaky02(sv.x + ad.x); e1 = leaky02(sv.y + ad.y);
            e2 = leaky02(sv.z + ad.z); e3 = leaky02(sv.w + ad.w);
        }
        float x0 = __expf(e0 - m0), x1 = __expf(e1 - m1);
        float x2 = __expf(e2 - m2), x3 = __expf(e3 - m3);
        if (e < MAXE) {
            ews[e] = x0; ews[MAXE + e] = x1; ews[2 * MAXE + e] = x2; ews[3 * MAXE + e] = x3;
        }
        d0 += x0; d1 += x1; d2 += x2; d3 += x3;
    }
#pragma unroll
    for (int o = 16; o; o >>= 1) {
        d0 += __shfl_xor_sync(full, d0, o);
        d1 += __shfl_xor_sync(full, d1, o);
        d2 += __shfl_xor_sync(full, d2, o);
        d3 += __shfl_xor_sync(full, d3, o);
    }
    float i0 = 1.0f / d0, i1 = 1.0f / d1, i2 = 1.0f / d2, i3 = 1.0f / d3;
    __syncwarp();

    float acc[3][8];
#pragma unroll
    for (int i = 0; i < 3; i++)
#pragma unroll
        for (int k = 0; k < 8; k++) acc[i][k] = 0.0f;

    for (int p = beg; p < end; ++p) {
        int e = p - beg;
        float a0, a1, a2, a3;
        if (e < MAXE) {
            a0 = ews[e] * i0;            a1 = ews[MAXE + e] * i1;
            a2 = ews[2 * MAXE + e] * i2; a3 = ews[3 * MAXE + e] * i3;
        } else {
            int s = g_csrc[p];
            float4 sv = *(const float4*)&g_asrc[s * 4];
            a0 = __expf(leaky02(sv.x + ad.x) - m0) * i0;
            a1 = __expf(leaky02(sv.y + ad.y) - m1) * i1;
            a2 = __expf(leaky02(sv.z + ad.z) - m2) * i2;
            a3 = __expf(leaky02(sv.w + ad.w) - m3) * i3;
        }
        const uint4* row = (const uint4*)(g_xwh + (size_t)g_csrc[p] * D);
#pragma unroll
        for (int i = 0; i < 3; i++) {
            int idx = i * 256 + lane * 8;
            int h = idx / HD;
            float a = (h == 0) ? a0 : (h == 1) ? a1 : (h == 2) ? a2 : a3;
            uint4 v = __ldg(&row[i * 32 + lane]);
            float2 q0 = __half22float2(*(__half2*)&v.x);
            float2 q1 = __half22float2(*(__half2*)&v.y);
            float2 q2 = __half22float2(*(__half2*)&v.z);
            float2 q3 = __half22float2(*(__half2*)&v.w);
            acc[i][0] = fmaf(a, q0.x, acc[i][0]);
            acc[i][1] = fmaf(a, q0.y, acc[i][1]);
            acc[i][2] = fmaf(a, q1.x, acc[i][2]);
            acc[i][3] = fmaf(a, q1.y, acc[i][3]);
            acc[i][4] = fmaf(a, q2.x, acc[i][4]);
            acc[i][5] = fmaf(a, q2.y, acc[i][5]);
            acc[i][6] = fmaf(a, q3.x, acc[i][6]);
            acc[i][7] = fmaf(a, q3.y, acc[i][7]);
        }
    }

    float s1 = 0.0f;
#pragma unroll
    for (int i = 0; i < 3; i++) {
        int idx = i * 256 + lane * 8;
        float4 b0 = *(const float4*)(bias + idx);
        float4 b1 = *(const float4*)(bias + idx + 4);
        acc[i][0] += b0.x; acc[i][1] += b0.y; acc[i][2] += b0.z; acc[i][3] += b0.w;
        acc[i][4] += b1.x; acc[i][5] += b1.y; acc[i][6] += b1.z; acc[i][7] += b1.w;
#pragma unroll
        for (int k = 0; k < 8; k++) s1 += acc[i][k];
    }
#pragma unroll
    for (int o = 16; o; o >>= 1) s1 += __shfl_xor_sync(full, s1, o);
    float mu = s1 * (1.0f / 768.0f);

    float s2 = 0.0f;
#pragma unroll
    for (int i = 0; i < 3; i++)
#pragma unroll
        for (int k = 0; k < 8; k++) { float dv = acc[i][k] - mu; s2 += dv * dv; }
#pragma unroll
    for (int o = 16; o; o >>= 1) s2 += __shfl_xor_sync(full, s2, o);
    float rstd = rsqrtf(s2 * (1.0f / 768.0f) + 1e-5f);

#pragma unroll
    for (int i = 0; i < 3; i++) {
        int idx = i * 256 + lane * 8;
        float4 g0 = *(const float4*)(gamma + idx);
        float4 g1 = *(const float4*)(gamma + idx + 4);
        float4 e0 = *(const float4*)(beta + idx);
        float4 e1 = *(const float4*)(beta + idx + 4);
        uint4 rv = *(const uint4*)(h_res + (size_t)n * D + idx);
        float2 r0 = __half22float2(*(__half2*)&rv.x);
        float2 r1 = __half22float2(*(__half2*)&rv.y);
        float2 r2 = __half22float2(*(__half2*)&rv.z);
        float2 r3 = __half22float2(*(__half2*)&rv.w);
        out[i][0] = fmaxf(fmaf((acc[i][0] - mu) * rstd, g0.x, e0.x), 0.0f) + r0.x;
        out[i][1] = fmaxf(fmaf((acc[i][1] - mu) * rstd, g0.y, e0.y), 0.0f) + r0.y;
        out[i][2] = fmaxf(fmaf((acc[i][2] - mu) * rstd, g0.z, e0.z), 0.0f) + r1.x;
        out[i][3] = fmaxf(fmaf((acc[i][3] - mu) * rstd, g0.w, e0.w), 0.0f) + r1.y;
        out[i][4] = fmaxf(fmaf((acc[i][4] - mu) * rstd, g1.x, e1.x), 0.0f) + r2.x;
        out[i][5] = fmaxf(fmaf((acc[i][5] - mu) * rstd, g1.y, e1.y), 0.0f) + r2.y;
        out[i][6] = fmaxf(fmaf((acc[i][6] - mu) * rstd, g1.z, e1.z), 0.0f) + r3.x;
        out[i][7] = fmaxf(fmaf((acc[i][7] - mu) * rstd, g1.w, e1.w), 0.0f) + r3.y;
    }
}

// ---------------- layer 1: smem score cache + 1-deep prefetch (R13 verbatim) ----------
__global__ __launch_bounds__(256) void gat_l1_kernel(
    const float* __restrict__ bias, const float* __restrict__ gamma,
    const float* __restrict__ beta, const __half* h_res, __half* h_out)
{
    __shared__ float ews_all[8 * 4 * MAXE];
    const unsigned full = 0xffffffffu;
    int wid  = threadIdx.x >> 5;
    int lane = threadIdx.x & 31;
    int n = blockIdx.x * 8 + wid;
    float* ews = &ews_all[wid * 4 * MAXE];

    int beg = g_rowptr[n], end = g_rowptr[n + 1];
    float4 ad = *(const float4*)&g_adst[n * 4];

    float m0 = -1e30f, m1 = -1e30f, m2 = -1e30f, m3 = -1e30f;
    for (int p = beg + lane; p < end; p += 32) {
        int s = g_csrc[p];
        float4 sv = *(const float4*)&g_asrc[s * 4];
        float e0 = leaky02(sv.x + ad.x), e1 = leaky02(sv.y + ad.y);
        float e2 = leaky02(sv.z + ad.z), e3 = leaky02(sv.w + ad.w);
        int e = p - beg;
        if (e < MAXE) {
            ews[e] = e0; ews[MAXE + e] = e1; ews[2 * MAXE + e] = e2; ews[3 * MAXE + e] = e3;
        }
        m0 = fmaxf(m0, e0); m1 = fmaxf(m1, e1); m2 = fmaxf(m2, e2); m3 = fmaxf(m3, e3);
    }
#pragma unroll
    for (int o = 16; o; o >>= 1) {
        m0 = fmaxf(m0, __shfl_xor_sync(full, m0, o));
        m1 = fmaxf(m1, __shfl_xor_sync(full, m1, o));
        m2 = fmaxf(m2, __shfl_xor_sync(full, m2, o));
        m3 = fmaxf(m3, __shfl_xor_sync(full, m3, o));
    }

    float d0 = 0, d1 = 0, d2 = 0, d3 = 0;
    for (int p = beg + lane; p < end; p += 32) {
        int e = p - beg;
        float e0, e1, e2, e3;
        if (e < MAXE) {
            e0 = ews[e]; e1 = ews[MAXE + e]; e2 = ews[2 * MAXE + e]; e3 = ews[3 * MAXE + e];
        } else {
            int s = g_csrc[p];
            float4 sv = *(const float4*)&g_asrc[s * 4];
            e0 = leaky02(sv.x + ad.x); e1 = leaky02(sv.y + ad.y);
            e2 = leaky02(sv.z + ad.z); e3 = leaky02(sv.w + ad.w);
        }
        float x0 = __expf(e0 - m0), x1 = __expf(e1 - m1);
        float x2 = __expf(e2 - m2), x3 = __expf(e3 - m3);
        if (e < MAXE) {
            ews[e] = x0; ews[MAXE + e] = x1; ews[2 * MAXE + e] = x2; ews[3 * MAXE + e] = x3;
        }
        d0 += x0; d1 += x1; d2 += x2; d3 += x3;
    }
#pragma unroll
    for (int o = 16; o; o >>= 1) {
        d0 += __shfl_xor_sync(full, d0, o);
        d1 += __shfl_xor_sync(full, d1, o);
        d2 += __shfl_xor_sync(full, d2, o);
        d3 += __shfl_xor_sync(full, d3, o);
    }
    float i0 = 1.0f / d0, i1 = 1.0f / d1, i2 = 1.0f / d2, i3 = 1.0f / d3;
    __syncwarp();

    float acc[3][8];
#pragma unroll
    for (int i = 0; i < 3; i++)
#pragma unroll
        for (int k = 0; k < 8; k++) acc[i][k] = 0.0f;

    const uint4* r0p = (const uint4*)(g_xwh + (size_t)g_csrc[beg] * D);
    uint4 f0 = __ldg(&r0p[lane]), f1 = __ldg(&r0p[32 + lane]), f2 = __ldg(&r0p[64 + lane]);

    for (int p = beg; p < end; ++p) {
        uint4 c0 = f0, c1 = f1, c2 = f2;
        int e = p - beg;
        float a0, a1, a2, a3;
        if (e < MAXE) {
            a0 = ews[e] * i0; a1 = ews[MAXE + e] * i1;
            a2 = ews[2 * MAXE + e] * i2; a3 = ews[3 * MAXE + e] * i3;
        } else {
            int s = g_csrc[p];
            float4 sv = *(const float4*)&g_asrc[s * 4];
            a0 = __expf(leaky02(sv.x + ad.x) - m0) * i0;
            a1 = __expf(leaky02(sv.y + ad.y) - m1) * i1;
            a2 = __expf(leaky02(sv.z + ad.z) - m2) * i2;
            a3 = __expf(leaky02(sv.w + ad.w) - m3) * i3;
        }
        if (p + 1 < end) {
            const uint4* rn = (const uint4*)(g_xwh + (size_t)g_csrc[p + 1] * D);
            f0 = __ldg(&rn[lane]); f1 = __ldg(&rn[32 + lane]); f2 = __ldg(&rn[64 + lane]);
        }
#pragma unroll
        for (int i = 0; i < 3; i++) {
            int idx = i * 256 + lane * 8;
            int h = idx / HD;
            float a = (h == 0) ? a0 : (h == 1) ? a1 : (h == 2) ? a2 : a3;
            uint4 v = (i == 0) ? c0 : (i == 1) ? c1 : c2;
            float2 q0 = __half22float2(*(__half2*)&v.x);
            float2 q1 = __half22float2(*(__half2*)&v.y);
            float2 q2 = __half22float2(*(__half2*)&v.z);
            float2 q3 = __half22float2(*(__half2*)&v.w);
            acc[i][0] = fmaf(a, q0.x, acc[i][0]);
            acc[i][1] = fmaf(a, q0.y, acc[i][1]);
            acc[i][2] = fmaf(a, q1.x, acc[i][2]);
            acc[i][3] = fmaf(a, q1.y, acc[i][3]);
            acc[i][4] = fmaf(a, q2.x, acc[i][4]);
            acc[i][5] = fmaf(a, q2.y, acc[i][5]);
            acc[i][6] = fmaf(a, q3.x, acc[i][6]);
            acc[i][7] = fmaf(a, q3.y, acc[i][7]);
        }
    }

    float s1 = 0.0f;
#pragma unroll
    for (int i = 0; i < 3; i++) {
        int idx = i * 256 + lane * 8;
        float4 b0 = *(const float4*)(bias + idx);
        float4 b1 = *(const float4*)(bias + idx + 4);
        acc[i][0] += b0.x; acc[i][1] += b0.y; acc[i][2] += b0.z; acc[i][3] += b0.w;
        acc[i][4] += b1.x; acc[i][5] += b1.y; acc[i][6] += b1.z; acc[i][7] += b1.w;
#pragma unroll
        for (int k = 0; k < 8; k++) s1 += acc[i][k];
    }
#pragma unroll
    for (int o = 16; o; o >>= 1) s1 += __shfl_xor_sync(full, s1, o);
    float mu = s1 * (1.0f / 768.0f);

    float s2 = 0.0f;
#pragma unroll
    for (int i = 0; i < 3; i++)
#pragma unroll
        for (int k = 0; k < 8; k++) { float dv = acc[i][k] - mu; s2 += dv * dv; }
#pragma unroll
    for (int o = 16; o; o >>= 1) s2 += __shfl_xor_sync(full, s2, o);
    float rstd = rsqrtf(s2 * (1.0f / 768.0f) + 1e-5f);

#pragma unroll
    for (int i = 0; i < 3; i++) {
        int idx = i * 256 + lane * 8;
        float4 g0 = *(const float4*)(gamma + idx);
        float4 g1 = *(const float4*)(gamma + idx + 4);
        float4 e0 = *(const float4*)(beta + idx);
        float4 e1 = *(const float4*)(beta + idx + 4);
        uint4 rv = *(const uint4*)(h_res + (size_t)n * D + idx);
        float2 r0 = __half22float2(*(__half2*)&rv.x);
        float2 r1 = __half22float2(*(__half2*)&rv.y);
        float2 r2 = __half22float2(*(__half2*)&rv.z);
        float2 r3 = __half22float2(*(__half2*)&rv.w);
        float o0 = fmaxf(fmaf((acc[i][0] - mu) * rstd, g0.x, e0.x), 0.0f) + r0.x;
        float o1 = fmaxf(fmaf((acc[i][1] - mu) * rstd, g0.y, e0.y), 0.0f) + r0.y;
        float o2 = fmaxf(fmaf((acc[i][2] - mu) * rstd, g0.z, e0.z), 0.0f) + r1.x;
        float o3 = fmaxf(fmaf((acc[i][3] - mu) * rstd, g0.w, e0.w), 0.0f) + r1.y;
        float o4 = fmaxf(fmaf((acc[i][4] - mu) * rstd, g1.x, e1.x), 0.0f) + r2.x;
        float o5 = fmaxf(fmaf((acc[i][5] - mu) * rstd, g1.y, e1.y), 0.0f) + r2.y;
        float o6 = fmaxf(fmaf((acc[i][6] - mu) * rstd, g1.z, e1.z), 0.0f) + r3.x;
        float o7 = fmaxf(fmaf((acc[i][7] - mu) * rstd, g1.w, e1.w), 0.0f) + r3.y;
        uint4 hv;
        *(__half2*)&hv.x = __floats2half2_rn(o0, o1);
        *(__half2*)&hv.y = __floats2half2_rn(o2, o3);
        *(__half2*)&hv.z = __floats2half2_rn(o4, o5);
        *(__half2*)&hv.w = __floats2half2_rn(o6, o7);
        *(uint4*)(h_out + (size_t)n * D + idx) = hv;
    }
}

// ---------------- layer 2 + pooling fused, now with smem score cache ----------------
constexpr int SM_L2POOL = 32 * D * 4 + 32 * 4 * MAXE * 4;   // 98304 + 16384 = 114688 B

__global__ __launch_bounds__(1024) void gat_l2_pool_kernel(
    const float* __restrict__ bias, const float* __restrict__ gamma,
    const float* __restrict__ beta, const __half* h_res, __half* pool_out)
{
    extern __shared__ float psm[];               // [32][768] pool buffer, then score cache
    float* ews_all = psm + 32 * D;
    int wid  = threadIdx.x >> 5;
    int lane = threadIdx.x & 31;
    int n = blockIdx.x * 32 + wid;
    float out[3][8];
    gat_node_compute_cached(n, lane, &ews_all[wid * 4 * MAXE], bias, gamma, beta, h_res, out);
#pragma unroll
    for (int i = 0; i < 3; i++) {
        int idx = i * 256 + lane * 8;
        *(float4*)&psm[wid * D + idx]     = make_float4(out[i][0], out[i][1], out[i][2], out[i][3]);
        *(float4*)&psm[wid * D + idx + 4] = make_float4(out[i][4], out[i][5], out[i][6], out[i][7]);
    }
    __syncthreads();
    if (threadIdx.x < D) {
        float s = 0.0f;
#pragma unroll
        for (int r = 0; r < 32; r++) s += psm[r * D + threadIdx.x];
        pool_out[(size_t)blockIdx.x * D + threadIdx.x] = __float2half_rn(s * (1.0f / 32.0f));
    }
}

// ---------------- launcher ----------------
extern "C" void kernel_launch(void* const* d_in, const int* in_sizes, int n_in,
                              void* d_out, int out_size)
{
    const float* x   = (const float*)d_in[0];
    const int*   ei  = (const int*)d_in[1];
    const float* W1  = (const float*)d_in[3];
    const float* as1 = (const float*)d_in[4];
    const float* ad1 = (const float*)d_in[5];
    const float* b1  = (const float*)d_in[6];
    const float* g1  = (const float*)d_in[7];
    const float* be1 = (const float*)d_in[8];
    const float* W2  = (const float*)d_in[9];
    const float* as2 = (const float*)d_in[10];
    const float* ad2 = (const float*)d_in[11];
    const float* b2  = (const float*)d_in[12];
    const float* g2  = (const float*)d_in[13];
    const float* be2 = (const float*)d_in[14];
    const float* Wo  = (const float*)d_in[15];
    const float* bo  = (const float*)d_in[16];
    float* out = (float*)d_out;

    float *p_as, *p_ad;
    __half *p_xh, *p_xwh, *p_wth, *p_hgh;
    cudaGetSymbolAddress((void**)&p_xh,  g_xh);
    cudaGetSymbolAddress((void**)&p_xwh, g_xwh);
    cudaGetSymbolAddress((void**)&p_wth, g_wth);
    cudaGetSymbolAddress((void**)&p_hgh, g_hgh);
    cudaGetSymbolAddress((void**)&p_as,  g_asrc);
    cudaGetSymbolAddress((void**)&p_ad,  g_adst);

    cudaFuncSetAttribute(mma_gemm_kernel,
                         cudaFuncAttributeMaxDynamicSharedMemorySize, SM_GEMM);
    cudaFuncSetAttribute(gat_l2_pool_kernel,
                         cudaFuncAttributeMaxDynamicSharedMemorySize, SM_L2POOL);

    dim3 tgrid(24, 24), tblk(32, 8);
    dim3 ggrid(D / 128, NN / 128);     // (6, 1024)

    conv_half_kernel<<<(NN * (D / 4)) / 256, 256>>>((const float4*)x, (__half2*)p_xh); // 0
    transpose768_kernel<<<tgrid, tblk>>>(W1, p_wth);                                    // 1
    init_deg_kernel<<<NN / 256, 256>>>();                                               // 2
    mma_gemm_kernel<<<ggrid, 256, SM_GEMM>>>(p_xh, p_wth, nullptr, p_xwh, nullptr,      // 3
                                             as1, ad1, p_as, p_ad);
    count_deg_kernel<<<EE / 256, 256>>>(ei);
    scan_phase1_kernel<<<NN / 1024, 1024>>>();
    scan_phase2_kernel<<<1, 128>>>();
    scan_phase3_kernel<<<(NN + 255) / 256, 256>>>();
    selfloop_init_kernel<<<NN / 256, 256>>>();
    scatter_edges_kernel<<<EE / 256, 256>>>(ei);

    // layer 1: residual fp16 x (in g_xh), write h1 fp16 IN PLACE into g_xh
    gat_l1_kernel<<<NN / 8, 256>>>(b1, g1, be1, p_xh, p_xh);

    // layer 2
    zero_attn_kernel<<<(NN * HH) / 256, 256>>>();
    transpose768_kernel<<<tgrid, tblk>>>(W2, p_wth);
    mma_gemm_kernel<<<ggrid, 256, SM_GEMM>>>(p_xh, p_wth, nullptr, p_xwh, nullptr,
                                             as2, ad2, p_as, p_ad);
    // layer 2 GAT + pooling fused (score-cached compute)
    gat_l2_pool_kernel<<<GG, 1024, SM_L2POOL>>>(b2, g2, be2, p_xh, p_hgh);

    // output projection (fp32 out + bias)
    transpose768_kernel<<<tgrid, tblk>>>(Wo, p_wth);
    mma_gemm_kernel<<<dim3(D / 128, GG / 128), 256, SM_GEMM>>>(p_hgh, p_wth, out, nullptr, bo,
                                                               nullptr, nullptr, nullptr, nullptr);
}

// round 15
// speedup vs baseline: 1.1466x; 1.0071x over previous
#include <cuda_runtime.h>
#include <cuda_fp16.h>
#include <cstdint>

// ---------------- problem constants ----------------
constexpr int NN = 131072;
constexpr int EE = 262144;
constexpr int GG = 4096;
constexpr int D  = 768;
constexpr int HH = 4;
constexpr int HD = 192;
constexpr int ET = EE + NN;
constexpr int MAXE = 32;

// ---------------- scratch (device globals) ----------------
__device__ __align__(256) __half g_xh[(size_t)NN * D];   // fp16: x, then h1 (in-place)
__device__ __align__(256) __half g_xwh[(size_t)NN * D];  // x @ W (fp16)
__device__ __align__(256) __half g_wth1[D * D];          // W1^T (fp16)
__device__ __align__(256) __half g_wth2[D * D];          // W2^T (fp16)
__device__ __align__(256) __half g_wtho[D * D];          // Wo^T (fp16)
__device__ __align__(256) __half g_hgh[GG * D];          // pooled (fp16)
__device__ float g_asrc[NN * HH];
__device__ float g_adst[NN * HH];
__device__ int   g_indeg[NN];
__device__ int   g_cursor[NN];
__device__ int   g_rowptr[NN + 1];
__device__ int   g_scan[NN];
__device__ int   g_bsum[256];
__device__ int   g_csrc[ET];

// ---------------- helpers ----------------
__device__ __forceinline__ void cp16(uint32_t saddr, const void* g) {
    asm volatile("cp.async.cg.shared.global [%0], [%1], 16;" :: "r"(saddr), "l"(g));
}
__device__ __forceinline__ uint32_t smem_u32(const void* p) {
    uint32_t a;
    asm("{ .reg .u64 t; cvta.to.shared.u64 t, %1; cvt.u32.u64 %0, t; }" : "=r"(a) : "l"(p));
    return a;
}
#define CP_COMMIT()  asm volatile("cp.async.commit_group;" ::: "memory")
#define CP_WAIT(n)   asm volatile("cp.async.wait_group %0;" :: "n"(n) : "memory")

__device__ __forceinline__ void mma16(float* d, const uint32_t* a, const uint32_t* b) {
    asm volatile(
        "mma.sync.aligned.m16n8k16.row.col.f32.f16.f16.f32 "
        "{%0,%1,%2,%3}, {%4,%5,%6,%7}, {%8,%9}, {%0,%1,%2,%3};"
        : "+f"(d[0]), "+f"(d[1]), "+f"(d[2]), "+f"(d[3])
        : "r"(a[0]), "r"(a[1]), "r"(a[2]), "r"(a[3]), "r"(b[0]), "r"(b[1]));
}

// ---------------- CSR construction ----------------
__global__ void init_indeg_kernel() {
    int i = blockIdx.x * blockDim.x + threadIdx.x;
    if (i < NN) g_indeg[i] = 1;
}
__global__ void zero_attn_kernel() {
    int i = blockIdx.x * blockDim.x + threadIdx.x;
    if (i < NN * HH) { g_asrc[i] = 0.0f; g_adst[i] = 0.0f; }
}
__global__ void count_deg_kernel(const int* __restrict__ ei) {
    int e = blockIdx.x * blockDim.x + threadIdx.x;
    if (e < EE) atomicAdd(&g_indeg[ei[EE + e]], 1);
}
__device__ __forceinline__ int block_incl_scan(int v, int* warp_sums) {
    const unsigned full = 0xffffffffu;
    int lane = threadIdx.x & 31, w = threadIdx.x >> 5, nw = blockDim.x >> 5;
#pragma unroll
    for (int o = 1; o < 32; o <<= 1) { int u = __shfl_up_sync(full, v, o); if (lane >= o) v += u; }
    if (lane == 31) warp_sums[w] = v;
    __syncthreads();
    if (w == 0) {
        int s = (lane < nw) ? warp_sums[lane] : 0;
#pragma unroll
        for (int o = 1; o < 32; o <<= 1) { int u = __shfl_up_sync(full, s, o); if (lane >= o) s += u; }
        if (lane < nw) warp_sums[lane] = s;
    }
    __syncthreads();
    if (w > 0) v += warp_sums[w - 1];
    return v;
}
__global__ void scan_phase1_kernel() {
    __shared__ int ws[32];
    int gid = blockIdx.x * 1024 + threadIdx.x;
    int incl = block_incl_scan(g_indeg[gid], ws);
    g_scan[gid] = incl;
    if (threadIdx.x == 1023) g_bsum[blockIdx.x] = incl;
}
__global__ void scan_phase2_kernel() {
    __shared__ int ws[32];
    int v = g_bsum[threadIdx.x];
    int incl = block_incl_scan(v, ws);
    g_bsum[threadIdx.x] = incl - v;
}
// fused: rowptr write + self-loop placement + cursor init
__global__ void scan3_selfloop_kernel() {
    int gid = blockIdx.x * blockDim.x + threadIdx.x;
    if (gid < NN) {
        int val = g_scan[gid] + g_bsum[gid >> 10];   // inclusive prefix
        g_rowptr[gid + 1] = val;
        int p = val - g_indeg[gid];                  // == rowptr[gid]
        g_csrc[p] = gid;                             // self loop first
        g_cursor[gid] = p + 1;
        if (gid == 0) g_rowptr[0] = 0;
    }
}
__global__ void scatter_edges_kernel(const int* __restrict__ ei) {
    int e = blockIdx.x * blockDim.x + threadIdx.x;
    if (e < EE) { int p = atomicAdd(&g_cursor[ei[EE + e]], 1); g_csrc[p] = ei[e]; }
}

// ---------------- fp32 -> fp16 conversion pass ----------------
__global__ void conv_half_kernel(const float4* __restrict__ in, __half2* __restrict__ out) {
    int i = blockIdx.x * blockDim.x + threadIdx.x;
    float4 v = in[i];
    out[2 * i]     = __floats2half2_rn(v.x, v.y);
    out[2 * i + 1] = __floats2half2_rn(v.z, v.w);
}

// ---------------- transpose 768x768 -> fp16 K-major ----------------
__global__ void transpose768_kernel(const float* __restrict__ W, __half* __restrict__ WT) {
    __shared__ float t[32][33];
    int bx = blockIdx.x * 32, by = blockIdx.y * 32;
    for (int i = threadIdx.y; i < 32; i += 8)
        t[i][threadIdx.x] = W[(size_t)(by + i) * D + bx + threadIdx.x];
    __syncthreads();
    for (int i = threadIdx.y; i < 32; i += 8)
        WT[(size_t)(bx + i) * D + by + threadIdx.x] = __float2half_rn(t[threadIdx.x][i]);
}

// ---------------- fp16 mma GEMM + fused attention-score epilogue ----------------
constexpr int BK   = 64;
constexpr int KSTG = D / BK;                      // 12
constexpr int RS   = 72;
constexpr int TILE_H  = 128 * RS;
constexpr int STAGE_H = 2 * TILE_H;
constexpr int SM_GEMM = 3 * STAGE_H * 2;          // 110,592 bytes

__global__ __launch_bounds__(256, 2) void mma_gemm_kernel(
    const __half* __restrict__ A, const __half* __restrict__ BT,
    float* __restrict__ Cf, __half* __restrict__ Ch, const float* __restrict__ bias,
    const float* __restrict__ att_s, const float* __restrict__ att_d,
    float* __restrict__ asrc, float* __restrict__ adst)
{
    extern __shared__ __half smh[];
    const int tid  = threadIdx.x;
    const int wid  = tid >> 5, lane = tid & 31;
    const int gid  = lane >> 2, tig = lane & 3;
    const int m0   = blockIdx.y * 128;
    const int n0   = blockIdx.x * 128;
    const int wm   = (wid & 1) * 64;
    const int wn   = (wid >> 1) * 32;

    const __half* ga = A  + (size_t)m0 * D;
    const __half* gb = BT + (size_t)n0 * D;
    const uint32_t sm_u = smem_u32(smh);

    auto load_stage = [&](int buf, int ks) {
        int k0 = ks * BK;
        uint32_t abase = sm_u + (uint32_t)buf * STAGE_H * 2;
        uint32_t bbase = abase + TILE_H * 2;
#pragma unroll
        for (int t = tid; t < 1024; t += 256) {
            int row = t >> 3, c = t & 7;
            uint32_t off = (uint32_t)(row * RS + c * 8) * 2;
            cp16(abase + off, ga + (size_t)row * D + k0 + c * 8);
            cp16(bbase + off, gb + (size_t)row * D + k0 + c * 8);
        }
        CP_COMMIT();
    };

    float acc[4][4][4];
#pragma unroll
    for (int i = 0; i < 4; i++)
#pragma unroll
        for (int j = 0; j < 4; j++)
#pragma unroll
            for (int q = 0; q < 4; q++) acc[i][j][q] = 0.0f;

    load_stage(0, 0);
    load_stage(1, 1);

    for (int s = 0; s < KSTG; ++s) {
        int buf = s % 3;
        if (s < KSTG - 1) CP_WAIT(1); else CP_WAIT(0);
        __syncthreads();

        const __half* Ab = smh + buf * STAGE_H + (wm + gid) * RS;
        const __half* Bb = smh + buf * STAGE_H + TILE_H + (wn + gid) * RS;
#pragma unroll
        for (int kk = 0; kk < 4; ++kk) {
            uint32_t af[4][4], bf[4][2];
#pragma unroll
            for (int i = 0; i < 4; ++i) {
                const __half* p = Ab + i * (16 * RS) + kk * 16 + tig * 2;
                af[i][0] = *(const uint32_t*)(p);
                af[i][1] = *(const uint32_t*)(p + 8 * RS);
                af[i][2] = *(const uint32_t*)(p + 8);
                af[i][3] = *(const uint32_t*)(p + 8 * RS + 8);
            }
#pragma unroll
            for (int j = 0; j < 4; ++j) {
                const __half* p = Bb + j * (8 * RS) + kk * 16 + tig * 2;
                bf[j][0] = *(const uint32_t*)(p);
                bf[j][1] = *(const uint32_t*)(p + 8);
            }
#pragma unroll
            for (int i = 0; i < 4; ++i)
#pragma unroll
                for (int j = 0; j < 4; ++j)
                    mma16(acc[i][j], af[i], bf[j]);
        }
        if (s + 2 < KSTG) load_stage((s + 2) % 3, s + 2);
    }

    if (att_s) {
        const unsigned full = 0xffffffffu;
        const int h = (n0 + wn) / HD;
        float asv[8], adv[8];
#pragma unroll
        for (int j = 0; j < 4; ++j) {
            int cb = n0 + wn + j * 8 + tig * 2;
            asv[j * 2 + 0] = att_s[cb];     asv[j * 2 + 1] = att_s[cb + 1];
            adv[j * 2 + 0] = att_d[cb];     adv[j * 2 + 1] = att_d[cb + 1];
        }
        float ps[8], pd[8];
#pragma unroll
        for (int i = 0; i < 4; ++i) {
            float s0 = 0, s1 = 0, d0 = 0, d1 = 0;
#pragma unroll
            for (int j = 0; j < 4; ++j) {
                s0 += acc[i][j][0] * asv[j * 2] + acc[i][j][1] * asv[j * 2 + 1];
                s1 += acc[i][j][2] * asv[j * 2] + acc[i][j][3] * asv[j * 2 + 1];
                d0 += acc[i][j][0] * adv[j * 2] + acc[i][j][1] * adv[j * 2 + 1];
                d1 += acc[i][j][2] * adv[j * 2] + acc[i][j][3] * adv[j * 2 + 1];
            }
            ps[i * 2] = s0; ps[i * 2 + 1] = s1; pd[i * 2] = d0; pd[i * 2 + 1] = d1;
        }
#pragma unroll
        for (int o = 1; o <= 2; o <<= 1)
#pragma unroll
            for (int k = 0; k < 8; ++k) {
                ps[k] += __shfl_xor_sync(full, ps[k], o);
                pd[k] += __shfl_xor_sync(full, pd[k], o);
            }
        if (tig == 0) {
#pragma unroll
            for (int i = 0; i < 4; ++i) {
                int r0 = m0 + wm + i * 16 + gid;
                atomicAdd(&asrc[r0 * HH + h],       ps[i * 2]);
                atomicAdd(&asrc[(r0 + 8) * HH + h], ps[i * 2 + 1]);
                atomicAdd(&adst[r0 * HH + h],       pd[i * 2]);
                atomicAdd(&adst[(r0 + 8) * HH + h], pd[i * 2 + 1]);
            }
        }
    }

    if (Ch) {
#pragma unroll
        for (int i = 0; i < 4; ++i) {
            int r = m0 + wm + i * 16 + gid;
#pragma unroll
            for (int j = 0; j < 4; ++j) {
                int cb = n0 + wn + j * 8 + tig * 2;
                *(__half2*)&Ch[(size_t)r * D + cb]       = __floats2half2_rn(acc[i][j][0], acc[i][j][1]);
                *(__half2*)&Ch[(size_t)(r + 8) * D + cb] = __floats2half2_rn(acc[i][j][2], acc[i][j][3]);
            }
        }
    } else {
#pragma unroll
        for (int i = 0; i < 4; ++i) {
            int r = m0 + wm + i * 16 + gid;
#pragma unroll
            for (int j = 0; j < 4; ++j) {
                int cb = n0 + wn + j * 8 + tig * 2;
                float bx = bias ? bias[cb] : 0.0f, by = bias ? bias[cb + 1] : 0.0f;
                float2 v0 = { acc[i][j][0] + bx, acc[i][j][1] + by };
                float2 v1 = { acc[i][j][2] + bx, acc[i][j][3] + by };
                *(float2*)&Cf[(size_t)r * D + cb]       = v0;
                *(float2*)&Cf[(size_t)(r + 8) * D + cb] = v1;
            }
        }
    }
}

__device__ __forceinline__ float leaky02(float e) { return e > 0.0f ? e : 0.2f * e; }

// ---------------- cached GAT node compute (no register prefetch; 1024-thread safe) ------
__device__ __forceinline__ void gat_node_compute_cached(
    int n, int lane, float* ews,
    const float* __restrict__ bias, const float* __restrict__ gamma,
    const float* __restrict__ beta, const __half* h_res, float out[3][8])
{
    const unsigned full = 0xffffffffu;
    int beg = g_rowptr[n], end = g_rowptr[n + 1];
    float4 ad = *(const float4*)&g_adst[n * 4];

    float m0 = -1e30f, m1 = -1e30f, m2 = -1e30f, m3 = -1e30f;
    for (int p = beg + lane; p < end; p += 32) {
        int s = g_csrc[p];
        float4 sv = *(const float4*)&g_asrc[s * 4];
        float e0 = leaky02(sv.x + ad.x), e1 = leaky02(sv.y + ad.y);
        float e2 = leaky02(sv.z + ad.z), e3 = leaky02(sv.w + ad.w);
        int e = p - beg;
        if (e < MAXE) {
            ews[e] = e0; ews[MAXE + e] = e1; ews[2 * MAXE + e] = e2; ews[3 * MAXE + e] = e3;
        }
        m0 = fmaxf(m0, e0); m1 = fmaxf(m1, e1); m2 = fmaxf(m2, e2); m3 = fmaxf(m3, e3);
    }
#pragma unroll
    for (int o = 16; o; o >>= 1) {
        m0 = fmaxf(m0, __shfl_xor_sync(full, m0, o));
        m1 = fmaxf(m1, __shfl_xor_sync(full, m1, o));
        m2 = fmaxf(m2, __shfl_xor_sync(full, m2, o));
        m3 = fmaxf(m3, __shfl_xor_sync(full, m3, o));
    }

    float d0 = 0, d1 = 0, d2 = 0, d3 = 0;
    for (int p = beg + lane; p < end; p += 32) {
        int e = p - beg;
        float e0, e1, e2, e3;
        if (e < MAXE) {
            e0 = ews[e]; e1 = ews[MAXE + e]; e2 = ews[2 * MAXE + e]; e3 = ews[3 * MAXE + e];
        } else {
            int s = g_csrc[p];
            float4 sv = *(const float4*)&g_asrc[s * 4];
            e0 = leaky02(sv.x + ad.x); e1 = leaky02(sv.y + ad.y);
            e2 = leaky02(sv.z + ad.z); e3 = leaky02(sv.w + ad.w);
        }
        float x0 = __expf(e0 - m0), x1 = __expf(e1 - m1);
        float x2 = __expf(e2 - m2), x3 = __expf(e3 - m3);
        if (e < MAXE) {
            ews[e] = x0; ews[MAXE + e] = x1; ews[2 * MAXE + e] = x2; ews[3 * MAXE + e] = x3;
        }
        d0 += x0; d1 += x1; d2 += x2; d3 += x3;
    }
#pragma unroll
    for (int o = 16; o; o >>= 1) {
        d0 += __shfl_xor_sync(full, d0, o);
        d1 += __shfl_xor_sync(full, d1, o);
        d2 += __shfl_xor_sync(full, d2, o);
        d3 += __shfl_xor_sync(full, d3, o);
    }
    float i0 = 1.0f / d0, i1 = 1.0f / d1, i2 = 1.0f / d2, i3 = 1.0f / d3;
    __syncwarp();

    float acc[3][8];
#pragma unroll
    for (int i = 0; i < 3; i++)
#pragma unroll
        for (int k = 0; k < 8; k++) acc[i][k] = 0.0f;

    for (int p = beg; p < end; ++p) {
        int e = p - beg;
        float a0, a1, a2, a3;
        if (e < MAXE) {
            a0 = ews[e] * i0;            a1 = ews[MAXE + e] * i1;
            a2 = ews[2 * MAXE + e] * i2; a3 = ews[3 * MAXE + e] * i3;
        } else {
            int s = g_csrc[p];
            float4 sv = *(const float4*)&g_asrc[s * 4];
            a0 = __expf(leaky02(sv.x + ad.x) - m0) * i0;
            a1 = __expf(leaky02(sv.y + ad.y) - m1) * i1;
            a2 = __expf(leaky02(sv.z + ad.z) - m2) * i2;
            a3 = __expf(leaky02(sv.w + ad.w) - m3) * i3;
        }
        const uint4* row = (const uint4*)(g_xwh + (size_t)g_csrc[p] * D);
#pragma unroll
        for (int i = 0; i < 3; i++) {
            int idx = i * 256 + lane * 8;
            int h = idx / HD;
            float a = (h == 0) ? a0 : (h == 1) ? a1 : (h == 2) ? a2 : a3;
            uint4 v = __ldg(&row[i * 32 + lane]);
            float2 q0 = __half22float2(*(__half2*)&v.x);
            float2 q1 = __half22float2(*(__half2*)&v.y);
            float2 q2 = __half22float2(*(__half2*)&v.z);
            float2 q3 = __half22float2(*(__half2*)&v.w);
            acc[i][0] = fmaf(a, q0.x, acc[i][0]);
            acc[i][1] = fmaf(a, q0.y, acc[i][1]);
            acc[i][2] = fmaf(a, q1.x, acc[i][2]);
            acc[i][3] = fmaf(a, q1.y, acc[i][3]);
            acc[i][4] = fmaf(a, q2.x, acc[i][4]);
            acc[i][5] = fmaf(a, q2.y, acc[i][5]);
            acc[i][6] = fmaf(a, q3.x, acc[i][6]);
            acc[i][7] = fmaf(a, q3.y, acc[i][7]);
        }
    }

    float s1 = 0.0f;
#pragma unroll
    for (int i = 0; i < 3; i++) {
        int idx = i * 256 + lane * 8;
        float4 b0 = *(const float4*)(bias + idx);
        float4 b1 = *(const float4*)(bias + idx + 4);
        acc[i][0] += b0.x; acc[i][1] += b0.y; acc[i][2] += b0.z; acc[i][3] += b0.w;
        acc[i][4] += b1.x; acc[i][5] += b1.y; acc[i][6] += b1.z; acc[i][7] += b1.w;
#pragma unroll
        for (int k = 0; k < 8; k++) s1 += acc[i][k];
    }
#pragma unroll
    for (int o = 16; o; o >>= 1) s1 += __shfl_xor_sync(full, s1, o);
    float mu = s1 * (1.0f / 768.0f);

    float s2 = 0.0f;
#pragma unroll
    for (int i = 0; i < 3; i++)
#pragma unroll
        for (int k = 0; k < 8; k++) { float dv = acc[i][k] - mu; s2 += dv * dv; }
#pragma unroll
    for (int o = 16; o; o >>= 1) s2 += __shfl_xor_sync(full, s2, o);
    float rstd = rsqrtf(s2 * (1.0f / 768.0f) + 1e-5f);

#pragma unroll
    for (int i = 0; i < 3; i++) {
        int idx = i * 256 + lane * 8;
        float4 g0 = *(const float4*)(gamma + idx);
        float4 g1 = *(const float4*)(gamma + idx + 4);
        float4 e0 = *(const float4*)(beta + idx);
        float4 e1 = *(const float4*)(beta + idx + 4);
        uint4 rv = *(const uint4*)(h_res + (size_t)n * D + idx);
        float2 r0 = __half22float2(*(__half2*)&rv.x);
        float2 r1 = __half22float2(*(__half2*)&rv.y);
        float2 r2 = __half22float2(*(__half2*)&rv.z);
        float2 r3 = __half22float2(*(__half2*)&rv.w);
        out[i][0] = fmaxf(fmaf((acc[i][0] - mu) * rstd, g0.x, e0.x), 0.0f) + r0.x;
        out[i][1] = fmaxf(fmaf((acc[i][1] - mu) * rstd, g0.y, e0.y), 0.0f) + r0.y;
        out[i][2] = fmaxf(fmaf((acc[i][2] - mu) * rstd, g0.z, e0.z), 0.0f) + r1.x;
        out[i][3] = fmaxf(fmaf((acc[i][3] - mu) * rstd, g0.w, e0.w), 0.0f) + r1.y;
        out[i][4] = fmaxf(fmaf((acc[i][4] - mu) * rstd, g1.x, e1.x), 0.0f) + r2.x;
        out[i][5] = fmaxf(fmaf((acc[i][5] - mu) * rstd, g1.y, e1.y), 0.0f) + r2.y;
        out[i][6] = fmaxf(fmaf((acc[i][6] - mu) * rstd, g1.z, e1.z), 0.0f) + r3.x;
        out[i][7] = fmaxf(fmaf((acc[i][7] - mu) * rstd, g1.w, e1.w), 0.0f) + r3.y;
    }
}

// ---------------- layer 1: smem score cache + 1-deep prefetch ----------
__global__ __launch_bounds__(256) void gat_l1_kernel(
    const float* __restrict__ bias, const float* __restrict__ gamma,
    const float* __restrict__ beta, const __half* h_res, __half* h_out)
{
    __shared__ float ews_all[8 * 4 * MAXE];
    const unsigned full = 0xffffffffu;
    int wid  = threadIdx.x >> 5;
    int lane = threadIdx.x & 31;
    int n = blockIdx.x * 8 + wid;
    float* ews = &ews_all[wid * 4 * MAXE];

    int beg = g_rowptr[n], end = g_rowptr[n + 1];
    float4 ad = *(const float4*)&g_adst[n * 4];

    float m0 = -1e30f, m1 = -1e30f, m2 = -1e30f, m3 = -1e30f;
    for (int p = beg + lane; p < end; p += 32) {
        int s = g_csrc[p];
        float4 sv = *(const float4*)&g_asrc[s * 4];
        float e0 = leaky02(sv.x + ad.x), e1 = leaky02(sv.y + ad.y);
        float e2 = leaky02(sv.z + ad.z), e3 = leaky02(sv.w + ad.w);
        int e = p - beg;
        if (e < MAXE) {
            ews[e] = e0; ews[MAXE + e] = e1; ews[2 * MAXE + e] = e2; ews[3 * MAXE + e] = e3;
        }
        m0 = fmaxf(m0, e0); m1 = fmaxf(m1, e1); m2 = fmaxf(m2, e2); m3 = fmaxf(m3, e3);
    }
#pragma unroll
    for (int o = 16; o; o >>= 1) {
        m0 = fmaxf(m0, __shfl_xor_sync(full, m0, o));
        m1 = fmaxf(m1, __shfl_xor_sync(full, m1, o));
        m2 = fmaxf(m2, __shfl_xor_sync(full, m2, o));
        m3 = fmaxf(m3, __shfl_xor_sync(full, m3, o));
    }

    float d0 = 0, d1 = 0, d2 = 0, d3 = 0;
    for (int p = beg + lane; p < end; p += 32) {
        int e = p - beg;
        float e0, e1, e2, e3;
        if (e < MAXE) {
            e0 = ews[e]; e1 = ews[MAXE + e]; e2 = ews[2 * MAXE + e]; e3 = ews[3 * MAXE + e];
        } else {
            int s = g_csrc[p];
            float4 sv = *(const float4*)&g_asrc[s * 4];
            e0 = leaky02(sv.x + ad.x); e1 = leaky02(sv.y + ad.y);
            e2 = leaky02(sv.z + ad.z); e3 = leaky02(sv.w + ad.w);
        }
        float x0 = __expf(e0 - m0), x1 = __expf(e1 - m1);
        float x2 = __expf(e2 - m2), x3 = __expf(e3 - m3);
        if (e < MAXE) {
            ews[e] = x0; ews[MAXE + e] = x1; ews[2 * MAXE + e] = x2; ews[3 * MAXE + e] = x3;
        }
        d0 += x0; d1 += x1; d2 += x2; d3 += x3;
    }
#pragma unroll
    for (int o = 16; o; o >>= 1) {
        d0 += __shfl_xor_sync(full, d0, o);
        d1 += __shfl_xor_sync(full, d1, o);
        d2 += __shfl_xor_sync(full, d2, o);
        d3 += __shfl_xor_sync(full, d3, o);
    }
    float i0 = 1.0f / d0, i1 = 1.0f / d1, i2 = 1.0f / d2, i3 = 1.0f / d3;
    __syncwarp();

    float acc[3][8];
#pragma unroll
    for (int i = 0; i < 3; i++)
#pragma unroll
        for (int k = 0; k < 8; k++) acc[i][k] = 0.0f;

    const uint4* r0p = (const uint4*)(g_xwh + (size_t)g_csrc[beg] * D);
    uint4 f0 = __ldg(&r0p[lane]), f1 = __ldg(&r0p[32 + lane]), f2 = __ldg(&r0p[64 + lane]);

    for (int p = beg; p < end; ++p) {
        uint4 c0 = f0, c1 = f1, c2 = f2;
        int e = p - beg;
        float a0, a1, a2, a3;
        if (e < MAXE) {
            a0 = ews[e] * i0; a1 = ews[MAXE + e] * i1;
            a2 = ews[2 * MAXE + e] * i2; a3 = ews[3 * MAXE + e] * i3;
        } else {
            int s = g_csrc[p];
            float4 sv = *(const float4*)&g_asrc[s * 4];
            a0 = __expf(leaky02(sv.x + ad.x) - m0) * i0;
            a1 = __expf(leaky02(sv.y + ad.y) - m1) * i1;
            a2 = __expf(leaky02(sv.z + ad.z) - m2) * i2;
            a3 = __expf(leaky02(sv.w + ad.w) - m3) * i3;
        }
        if (p + 1 < end) {
            const uint4* rn = (const uint4*)(g_xwh + (size_t)g_csrc[p + 1] * D);
            f0 = __ldg(&rn[lane]); f1 = __ldg(&rn[32 + lane]); f2 = __ldg(&rn[64 + lane]);
        }
#pragma unroll
        for (int i = 0; i < 3; i++) {
            int idx = i * 256 + lane * 8;
            int h = idx / HD;
            float a = (h == 0) ? a0 : (h == 1) ? a1 : (h == 2) ? a2 : a3;
            uint4 v = (i == 0) ? c0 : (i == 1) ? c1 : c2;
            float2 q0 = __half22float2(*(__half2*)&v.x);
            float2 q1 = __half22float2(*(__half2*)&v.y);
            float2 q2 = __half22float2(*(__half2*)&v.z);
            float2 q3 = __half22float2(*(__half2*)&v.w);
            acc[i][0] = fmaf(a, q0.x, acc[i][0]);
            acc[i][1] = fmaf(a, q0.y, acc[i][1]);
            acc[i][2] = fmaf(a, q1.x, acc[i][2]);
            acc[i][3] = fmaf(a, q1.y, acc[i][3]);
            acc[i][4] = fmaf(a, q2.x, acc[i][4]);
            acc[i][5] = fmaf(a, q2.y, acc[i][5]);
            acc[i][6] = fmaf(a, q3.x, acc[i][6]);
            acc[i][7] = fmaf(a, q3.y, acc[i][7]);
        }
    }

    float s1 = 0.0f;
#pragma unroll
    for (int i = 0; i < 3; i++) {
        int idx = i * 256 + lane * 8;
        float4 b0 = *(const float4*)(bias + idx);
        float4 b1 = *(const float4*)(bias + idx + 4);
        acc[i][0] += b0.x; acc[i][1] += b0.y; acc[i][2] += b0.z; acc[i][3] += b0.w;
        acc[i][4] += b1.x; acc[i][5] += b1.y; acc[i][6] += b1.z; acc[i][7] += b1.w;
#pragma unroll
        for (int k = 0; k < 8; k++) s1 += acc[i][k];
    }
#pragma unroll
    for (int o = 16; o; o >>= 1) s1 += __shfl_xor_sync(full, s1, o);
    float mu = s1 * (1.0f / 768.0f);

    float s2 = 0.0f;
#pragma unroll
    for (int i = 0; i < 3; i++)
#pragma unroll
        for (int k = 0; k < 8; k++) { float dv = acc[i][k] - mu; s2 += dv * dv; }
#pragma unroll
    for (int o = 16; o; o >>= 1) s2 += __shfl_xor_sync(full, s2, o);
    float rstd = rsqrtf(s2 * (1.0f / 768.0f) + 1e-5f);

#pragma unroll
    for (int i = 0; i < 3; i++) {
        int idx = i * 256 + lane * 8;
        float4 g0 = *(const float4*)(gamma + idx);
        float4 g1 = *(const float4*)(gamma + idx + 4);
        float4 e0 = *(const float4*)(beta + idx);
        float4 e1 = *(const float4*)(beta + idx + 4);
        uint4 rv = *(const uint4*)(h_res + (size_t)n * D + idx);
        float2 r0 = __half22float2(*(__half2*)&rv.x);
        float2 r1 = __half22float2(*(__half2*)&rv.y);
        float2 r2 = __half22float2(*(__half2*)&rv.z);
        float2 r3 = __half22float2(*(__half2*)&rv.w);
        float o0 = fmaxf(fmaf((acc[i][0] - mu) * rstd, g0.x, e0.x), 0.0f) + r0.x;
        float o1 = fmaxf(fmaf((acc[i][1] - mu) * rstd, g0.y, e0.y), 0.0f) + r0.y;
        float o2 = fmaxf(fmaf((acc[i][2] - mu) * rstd, g0.z, e0.z), 0.0f) + r1.x;
        float o3 = fmaxf(fmaf((acc[i][3] - mu) * rstd, g0.w, e0.w), 0.0f) + r1.y;
        float o4 = fmaxf(fmaf((acc[i][4] - mu) * rstd, g1.x, e1.x), 0.0f) + r2.x;
        float o5 = fmaxf(fmaf((acc[i][5] - mu) * rstd, g1.y, e1.y), 0.0f) + r2.y;
        float o6 = fmaxf(fmaf((acc[i][6] - mu) * rstd, g1.z, e1.z), 0.0f) + r3.x;
        float o7 = fmaxf(fmaf((acc[i][7] - mu) * rstd, g1.w, e1.w), 0.0f) + r3.y;
        uint4 hv;
        *(__half2*)&hv.x = __floats2half2_rn(o0, o1);
        *(__half2*)&hv.y = __floats2half2_rn(o2, o3);
        *(__half2*)&hv.z = __floats2half2_rn(o4, o5);
        *(__half2*)&hv.w = __floats2half2_rn(o6, o7);
        *(uint4*)(h_out + (size_t)n * D + idx) = hv;
    }
}

// ---------------- layer 2 + pooling fused (score-cached) ----------------
constexpr int SM_L2POOL = 32 * D * 4 + 32 * 4 * MAXE * 4;   // 114,688 B

__global__ __launch_bounds__(1024) void gat_l2_pool_kernel(
    const float* __restrict__ bias, const float* __restrict__ gamma,
    const float* __restrict__ beta, const __half* h_res, __half* pool_out)
{
    extern __shared__ float psm[];
    float* ews_all = psm + 32 * D;
    int wid  = threadIdx.x >> 5;
    int lane = threadIdx.x & 31;
    int n = blockIdx.x * 32 + wid;
    float out[3][8];
    gat_node_compute_cached(n, lane, &ews_all[wid * 4 * MAXE], bias, gamma, beta, h_res, out);
#pragma unroll
    for (int i = 0; i < 3; i++) {
        int idx = i * 256 + lane * 8;
        *(float4*)&psm[wid * D + idx]     = make_float4(out[i][0], out[i][1], out[i][2], out[i][3]);
        *(float4*)&psm[wid * D + idx + 4] = make_float4(out[i][4], out[i][5], out[i][6], out[i][7]);
    }
    __syncthreads();
    if (threadIdx.x < D) {
        float s = 0.0f;
#pragma unroll
        for (int r = 0; r < 32; r++) s += psm[r * D + threadIdx.x];
        pool_out[(size_t)blockIdx.x * D + threadIdx.x] = __float2half_rn(s * (1.0f / 32.0f));
    }
}

// ---------------- launcher (multi-stream fork/join, graph-capturable) ----------------
extern "C" void kernel_launch(void* const* d_in, const int* in_sizes, int n_in,
                              void* d_out, int out_size)
{
    const float* x   = (const float*)d_in[0];
    const int*   ei  = (const int*)d_in[1];
    const float* W1  = (const float*)d_in[3];
    const float* as1 = (const float*)d_in[4];
    const float* ad1 = (const float*)d_in[5];
    const float* b1  = (const float*)d_in[6];
    const float* g1  = (const float*)d_in[7];
    const float* be1 = (const float*)d_in[8];
    const float* W2  = (const float*)d_in[9];
    const float* as2 = (const float*)d_in[10];
    const float* ad2 = (const float*)d_in[11];
    const float* b2  = (const float*)d_in[12];
    const float* g2  = (const float*)d_in[13];
    const float* be2 = (const float*)d_in[14];
    const float* Wo  = (const float*)d_in[15];
    const float* bo  = (const float*)d_in[16];
    float* out = (float*)d_out;

    float *p_as, *p_ad;
    __half *p_xh, *p_xwh, *p_wt1, *p_wt2, *p_wto, *p_hgh;
    cudaGetSymbolAddress((void**)&p_xh,  g_xh);
    cudaGetSymbolAddress((void**)&p_xwh, g_xwh);
    cudaGetSymbolAddress((void**)&p_wt1, g_wth1);
    cudaGetSymbolAddress((void**)&p_wt2, g_wth2);
    cudaGetSymbolAddress((void**)&p_wto, g_wtho);
    cudaGetSymbolAddress((void**)&p_hgh, g_hgh);
    cudaGetSymbolAddress((void**)&p_as,  g_asrc);
    cudaGetSymbolAddress((void**)&p_ad,  g_adst);

    cudaFuncSetAttribute(mma_gemm_kernel,
                         cudaFuncAttributeMaxDynamicSharedMemorySize, SM_GEMM);
    cudaFuncSetAttribute(gat_l2_pool_kernel,
                         cudaFuncAttributeMaxDynamicSharedMemorySize, SM_L2POOL);

    // one-time stream/event setup (first call = uncaptured correctness run)
    static cudaStream_t s2 = nullptr;
    static cudaEvent_t evFork = nullptr, evSide = nullptr;
    if (!s2) {
        cudaStreamCreateWithFlags(&s2, cudaStreamNonBlocking);
        cudaEventCreateWithFlags(&evFork, cudaEventDisableTiming);
        cudaEventCreateWithFlags(&evSide, cudaEventDisableTiming);
    }

    dim3 tgrid(24, 24), tblk(32, 8);
    dim3 ggrid(D / 128, NN / 128);     // (6, 1024)

    // ---- fork: side stream does W2/Wo transposes + full CSR build ----
    cudaEventRecord(evFork, 0);
    cudaStreamWaitEvent(s2, evFork, 0);
    transpose768_kernel<<<tgrid, tblk, 0, s2>>>(W2, p_wt2);
    transpose768_kernel<<<tgrid, tblk, 0, s2>>>(Wo, p_wto);
    init_indeg_kernel<<<NN / 256, 256, 0, s2>>>();
    count_deg_kernel<<<EE / 256, 256, 0, s2>>>(ei);
    scan_phase1_kernel<<<NN / 1024, 1024, 0, s2>>>();
    scan_phase2_kernel<<<1, 128, 0, s2>>>();
    scan3_selfloop_kernel<<<(NN + 255) / 256, 256, 0, s2>>>();
    scatter_edges_kernel<<<EE / 256, 256, 0, s2>>>(ei);
    cudaEventRecord(evSide, s2);

    // ---- main stream: conv + W1 transpose + zero attn + GEMM1 ----
    conv_half_kernel<<<(NN * (D / 4)) / 256, 256>>>((const float4*)x, (__half2*)p_xh);
    transpose768_kernel<<<tgrid, tblk>>>(W1, p_wt1);
    zero_attn_kernel<<<(NN * HH) / 256, 256>>>();
    mma_gemm_kernel<<<ggrid, 256, SM_GEMM>>>(p_xh, p_wt1, nullptr, p_xwh, nullptr,
                                             as1, ad1, p_as, p_ad);

    // ---- join: CSR + W2/Wo ready ----
    cudaStreamWaitEvent(0, evSide, 0);

    // layer 1: residual fp16 x (in g_xh), write h1 fp16 IN PLACE into g_xh
    gat_l1_kernel<<<NN / 8, 256>>>(b1, g1, be1, p_xh, p_xh);

    // layer 2
    zero_attn_kernel<<<(NN * HH) / 256, 256>>>();
    mma_gemm_kernel<<<ggrid, 256, SM_GEMM>>>(p_xh, p_wt2, nullptr, p_xwh, nullptr,
                                             as2, ad2, p_as, p_ad);
    gat_l2_pool_kernel<<<GG, 1024, SM_L2POOL>>>(b2, g2, be2, p_xh, p_hgh);

    // output projection (fp32 out + bias)
    mma_gemm_kernel<<<dim3(D / 128, GG / 128), 256, SM_GEMM>>>(p_hgh, p_wto, out, nullptr, bo,
                                                               nullptr, nullptr, nullptr, nullptr);
}

// round 16
// speedup vs baseline: 1.1484x; 1.0016x over previous
#include <cuda_runtime.h>
#include <cuda_fp16.h>
#include <cstdint>

// ---------------- problem constants ----------------
constexpr int NN = 131072;
constexpr int EE = 262144;
constexpr int GG = 4096;
constexpr int D  = 768;
constexpr int HH = 4;
constexpr int HD = 192;
constexpr int ET = EE + NN;
constexpr int MAXE = 32;

// ---------------- scratch (device globals) ----------------
__device__ __align__(256) __half g_xh[(size_t)NN * D];   // fp16: x, then h1 (in-place)
__device__ __align__(256) __half g_xwh[(size_t)NN * D];  // x @ W (fp16)
__device__ __align__(256) __half g_wth1[D * D];
__device__ __align__(256) __half g_wth2[D * D];
__device__ __align__(256) __half g_wtho[D * D];
__device__ __align__(256) __half g_hgh[GG * D];
__device__ float g_asrc1[NN * HH];
__device__ float g_adst1[NN * HH];
__device__ float g_asrc2[NN * HH];
__device__ float g_adst2[NN * HH];
__device__ int   g_indeg[NN];
__device__ int   g_cursor[NN];
__device__ int   g_rowptr[NN + 1];
__device__ int   g_scan[NN];
__device__ int   g_bsum[256];
__device__ int   g_csrc[ET];

// ---------------- helpers ----------------
__device__ __forceinline__ void cp16(uint32_t saddr, const void* g) {
    asm volatile("cp.async.cg.shared.global [%0], [%1], 16;" :: "r"(saddr), "l"(g));
}
__device__ __forceinline__ uint32_t smem_u32(const void* p) {
    uint32_t a;
    asm("{ .reg .u64 t; cvta.to.shared.u64 t, %1; cvt.u32.u64 %0, t; }" : "=r"(a) : "l"(p));
    return a;
}
#define CP_COMMIT()  asm volatile("cp.async.commit_group;" ::: "memory")
#define CP_WAIT(n)   asm volatile("cp.async.wait_group %0;" :: "n"(n) : "memory")

__device__ __forceinline__ void mma16(float* d, const uint32_t* a, const uint32_t* b) {
    asm volatile(
        "mma.sync.aligned.m16n8k16.row.col.f32.f16.f16.f32 "
        "{%0,%1,%2,%3}, {%4,%5,%6,%7}, {%8,%9}, {%0,%1,%2,%3};"
        : "+f"(d[0]), "+f"(d[1]), "+f"(d[2]), "+f"(d[3])
        : "r"(a[0]), "r"(a[1]), "r"(a[2]), "r"(a[3]), "r"(b[0]), "r"(b[1]));
}

// ---------------- CSR construction ----------------
__global__ void init_indeg_kernel() {
    int i = blockIdx.x * blockDim.x + threadIdx.x;
    if (i < NN) g_indeg[i] = 1;
}
__global__ void zero_attn_kernel(float* __restrict__ a, float* __restrict__ d) {
    int i = blockIdx.x * blockDim.x + threadIdx.x;
    if (i < NN * HH) { a[i] = 0.0f; d[i] = 0.0f; }
}
__global__ void count_deg_kernel(const int* __restrict__ ei) {
    int e = blockIdx.x * blockDim.x + threadIdx.x;
    if (e < EE) atomicAdd(&g_indeg[ei[EE + e]], 1);
}
__device__ __forceinline__ int block_incl_scan(int v, int* warp_sums) {
    const unsigned full = 0xffffffffu;
    int lane = threadIdx.x & 31, w = threadIdx.x >> 5, nw = blockDim.x >> 5;
#pragma unroll
    for (int o = 1; o < 32; o <<= 1) { int u = __shfl_up_sync(full, v, o); if (lane >= o) v += u; }
    if (lane == 31) warp_sums[w] = v;
    __syncthreads();
    if (w == 0) {
        int s = (lane < nw) ? warp_sums[lane] : 0;
#pragma unroll
        for (int o = 1; o < 32; o <<= 1) { int u = __shfl_up_sync(full, s, o); if (lane >= o) s += u; }
        if (lane < nw) warp_sums[lane] = s;
    }
    __syncthreads();
    if (w > 0) v += warp_sums[w - 1];
    return v;
}
__global__ void scan_phase1_kernel() {
    __shared__ int ws[32];
    int gid = blockIdx.x * 1024 + threadIdx.x;
    int incl = block_incl_scan(g_indeg[gid], ws);
    g_scan[gid] = incl;
    if (threadIdx.x == 1023) g_bsum[blockIdx.x] = incl;
}
__global__ void scan_phase2_kernel() {
    __shared__ int ws[32];
    int v = g_bsum[threadIdx.x];
    int incl = block_incl_scan(v, ws);
    g_bsum[threadIdx.x] = incl - v;
}
__global__ void scan3_selfloop_kernel() {
    int gid = blockIdx.x * blockDim.x + threadIdx.x;
    if (gid < NN) {
        int val = g_scan[gid] + g_bsum[gid >> 10];
        g_rowptr[gid + 1] = val;
        int p = val - g_indeg[gid];
        g_csrc[p] = gid;
        g_cursor[gid] = p + 1;
        if (gid == 0) g_rowptr[0] = 0;
    }
}
__global__ void scatter_edges_kernel(const int* __restrict__ ei) {
    int e = blockIdx.x * blockDim.x + threadIdx.x;
    if (e < EE) { int p = atomicAdd(&g_cursor[ei[EE + e]], 1); g_csrc[p] = ei[e]; }
}

// ---------------- fp32 -> fp16 conversion pass ----------------
__global__ void conv_half_kernel(const float4* __restrict__ in, __half2* __restrict__ out) {
    int i = blockIdx.x * blockDim.x + threadIdx.x;
    float4 v = in[i];
    out[2 * i]     = __floats2half2_rn(v.x, v.y);
    out[2 * i + 1] = __floats2half2_rn(v.z, v.w);
}

// ---------------- transpose 768x768 -> fp16 K-major ----------------
__global__ void transpose768_kernel(const float* __restrict__ W, __half* __restrict__ WT) {
    __shared__ float t[32][33];
    int bx = blockIdx.x * 32, by = blockIdx.y * 32;
    for (int i = threadIdx.y; i < 32; i += 8)
        t[i][threadIdx.x] = W[(size_t)(by + i) * D + bx + threadIdx.x];
    __syncthreads();
    for (int i = threadIdx.y; i < 32; i += 8)
        WT[(size_t)(bx + i) * D + by + threadIdx.x] = __float2half_rn(t[threadIdx.x][i]);
}

// ---------------- fp16 mma GEMM + fused attention-score epilogue ----------------
constexpr int BK   = 64;
constexpr int KSTG = D / BK;                      // 12
constexpr int RS   = 72;
constexpr int TILE_H  = 128 * RS;
constexpr int STAGE_H = 2 * TILE_H;
constexpr int SM_GEMM = 3 * STAGE_H * 2;          // 110,592 bytes

__global__ __launch_bounds__(256, 2) void mma_gemm_kernel(
    const __half* __restrict__ A, const __half* __restrict__ BT,
    float* __restrict__ Cf, __half* __restrict__ Ch, const float* __restrict__ bias,
    const float* __restrict__ att_s, const float* __restrict__ att_d,
    float* __restrict__ asrc, float* __restrict__ adst)
{
    extern __shared__ __half smh[];
    const int tid  = threadIdx.x;
    const int wid  = tid >> 5, lane = tid & 31;
    const int gid  = lane >> 2, tig = lane & 3;
    const int m0   = blockIdx.y * 128;
    const int n0   = blockIdx.x * 128;
    const int wm   = (wid & 1) * 64;
    const int wn   = (wid >> 1) * 32;

    const __half* ga = A  + (size_t)m0 * D;
    const __half* gb = BT + (size_t)n0 * D;
    const uint32_t sm_u = smem_u32(smh);

    auto load_stage = [&](int buf, int ks) {
        int k0 = ks * BK;
        uint32_t abase = sm_u + (uint32_t)buf * STAGE_H * 2;
        uint32_t bbase = abase + TILE_H * 2;
#pragma unroll
        for (int t = tid; t < 1024; t += 256) {
            int row = t >> 3, c = t & 7;
            uint32_t off = (uint32_t)(row * RS + c * 8) * 2;
            cp16(abase + off, ga + (size_t)row * D + k0 + c * 8);
            cp16(bbase + off, gb + (size_t)row * D + k0 + c * 8);
        }
        CP_COMMIT();
    };

    float acc[4][4][4];
#pragma unroll
    for (int i = 0; i < 4; i++)
#pragma unroll
        for (int j = 0; j < 4; j++)
#pragma unroll
            for (int q = 0; q < 4; q++) acc[i][j][q] = 0.0f;

    load_stage(0, 0);
    load_stage(1, 1);

    for (int s = 0; s < KSTG; ++s) {
        int buf = s % 3;
        if (s < KSTG - 1) CP_WAIT(1); else CP_WAIT(0);
        __syncthreads();

        const __half* Ab = smh + buf * STAGE_H + (wm + gid) * RS;
        const __half* Bb = smh + buf * STAGE_H + TILE_H + (wn + gid) * RS;
#pragma unroll
        for (int kk = 0; kk < 4; ++kk) {
            uint32_t af[4][4], bf[4][2];
#pragma unroll
            for (int i = 0; i < 4; ++i) {
                const __half* p = Ab + i * (16 * RS) + kk * 16 + tig * 2;
                af[i][0] = *(const uint32_t*)(p);
                af[i][1] = *(const uint32_t*)(p + 8 * RS);
                af[i][2] = *(const uint32_t*)(p + 8);
                af[i][3] = *(const uint32_t*)(p + 8 * RS + 8);
            }
#pragma unroll
            for (int j = 0; j < 4; ++j) {
                const __half* p = Bb + j * (8 * RS) + kk * 16 + tig * 2;
                bf[j][0] = *(const uint32_t*)(p);
                bf[j][1] = *(const uint32_t*)(p + 8);
            }
#pragma unroll
            for (int i = 0; i < 4; ++i)
#pragma unroll
                for (int j = 0; j < 4; ++j)
                    mma16(acc[i][j], af[i], bf[j]);
        }
        if (s + 2 < KSTG) load_stage((s + 2) % 3, s + 2);
    }

    if (att_s) {
        const unsigned full = 0xffffffffu;
        const int h = (n0 + wn) / HD;
        float asv[8], adv[8];
#pragma unroll
        for (int j = 0; j < 4; ++j) {
            int cb = n0 + wn + j * 8 + tig * 2;
            asv[j * 2 + 0] = att_s[cb];     asv[j * 2 + 1] = att_s[cb + 1];
            adv[j * 2 + 0] = att_d[cb];     adv[j * 2 + 1] = att_d[cb + 1];
        }
        float ps[8], pd[8];
#pragma unroll
        for (int i = 0; i < 4; ++i) {
            float s0 = 0, s1 = 0, d0 = 0, d1 = 0;
#pragma unroll
            for (int j = 0; j < 4; ++j) {
                s0 += acc[i][j][0] * asv[j * 2] + acc[i][j][1] * asv[j * 2 + 1];
                s1 += acc[i][j][2] * asv[j * 2] + acc[i][j][3] * asv[j * 2 + 1];
                d0 += acc[i][j][0] * adv[j * 2] + acc[i][j][1] * adv[j * 2 + 1];
                d1 += acc[i][j][2] * adv[j * 2] + acc[i][j][3] * adv[j * 2 + 1];
            }
            ps[i * 2] = s0; ps[i * 2 + 1] = s1; pd[i * 2] = d0; pd[i * 2 + 1] = d1;
        }
#pragma unroll
        for (int o = 1; o <= 2; o <<= 1)
#pragma unroll
            for (int k = 0; k < 8; ++k) {
                ps[k] += __shfl_xor_sync(full, ps[k], o);
                pd[k] += __shfl_xor_sync(full, pd[k], o);
            }
        if (tig == 0) {
#pragma unroll
            for (int i = 0; i < 4; ++i) {
                int r0 = m0 + wm + i * 16 + gid;
                atomicAdd(&asrc[r0 * HH + h],       ps[i * 2]);
                atomicAdd(&asrc[(r0 + 8) * HH + h], ps[i * 2 + 1]);
                atomicAdd(&adst[r0 * HH + h],       pd[i * 2]);
                atomicAdd(&adst[(r0 + 8) * HH + h], pd[i * 2 + 1]);
            }
        }
    }

    if (Ch) {
#pragma unroll
        for (int i = 0; i < 4; ++i) {
            int r = m0 + wm + i * 16 + gid;
#pragma unroll
            for (int j = 0; j < 4; ++j) {
                int cb = n0 + wn + j * 8 + tig * 2;
                *(__half2*)&Ch[(size_t)r * D + cb]       = __floats2half2_rn(acc[i][j][0], acc[i][j][1]);
                *(__half2*)&Ch[(size_t)(r + 8) * D + cb] = __floats2half2_rn(acc[i][j][2], acc[i][j][3]);
            }
        }
    } else {
#pragma unroll
        for (int i = 0; i < 4; ++i) {
            int r = m0 + wm + i * 16 + gid;
#pragma unroll
            for (int j = 0; j < 4; ++j) {
                int cb = n0 + wn + j * 8 + tig * 2;
                float bx = bias ? bias[cb] : 0.0f, by = bias ? bias[cb + 1] : 0.0f;
                float2 v0 = { acc[i][j][0] + bx, acc[i][j][1] + by };
                float2 v1 = { acc[i][j][2] + bx, acc[i][j][3] + by };
                *(float2*)&Cf[(size_t)r * D + cb]       = v0;
                *(float2*)&Cf[(size_t)(r + 8) * D + cb] = v1;
            }
        }
    }
}

__device__ __forceinline__ float leaky02(float e) { return e > 0.0f ? e : 0.2f * e; }

// ---------------- cached GAT node compute (no register prefetch; 1024-thread safe) ------
__device__ __forceinline__ void gat_node_compute_cached(
    int n, int lane, float* ews,
    const float* __restrict__ asrc, const float* __restrict__ adst,
    const float* __restrict__ bias, const float* __restrict__ gamma,
    const float* __restrict__ beta, const __half* h_res, float out[3][8])
{
    const unsigned full = 0xffffffffu;
    int beg = g_rowptr[n], end = g_rowptr[n + 1];
    float4 ad = *(const float4*)&adst[n * 4];

    float m0 = -1e30f, m1 = -1e30f, m2 = -1e30f, m3 = -1e30f;
    for (int p = beg + lane; p < end; p += 32) {
        int s = g_csrc[p];
        float4 sv = *(const float4*)&asrc[s * 4];
        float e0 = leaky02(sv.x + ad.x), e1 = leaky02(sv.y + ad.y);
        float e2 = leaky02(sv.z + ad.z), e3 = leaky02(sv.w + ad.w);
        int e = p - beg;
        if (e < MAXE) {
            ews[e] = e0; ews[MAXE + e] = e1; ews[2 * MAXE + e] = e2; ews[3 * MAXE + e] = e3;
        }
        m0 = fmaxf(m0, e0); m1 = fmaxf(m1, e1); m2 = fmaxf(m2, e2); m3 = fmaxf(m3, e3);
    }
#pragma unroll
    for (int o = 16; o; o >>= 1) {
        m0 = fmaxf(m0, __shfl_xor_sync(full, m0, o));
        m1 = fmaxf(m1, __shfl_xor_sync(full, m1, o));
        m2 = fmaxf(m2, __shfl_xor_sync(full, m2, o));
        m3 = fmaxf(m3, __shfl_xor_sync(full, m3, o));
    }

    float d0 = 0, d1 = 0, d2 = 0, d3 = 0;
    for (int p = beg + lane; p < end; p += 32) {
        int e = p - beg;
        float e0, e1, e2, e3;
        if (e < MAXE) {
            e0 = ews[e]; e1 = ews[MAXE + e]; e2 = ews[2 * MAXE + e]; e3 = ews[3 * MAXE + e];
        } else {
            int s = g_csrc[p];
            float4 sv = *(const float4*)&asrc[s * 4];
            e0 = leaky02(sv.x + ad.x); e1 = leaky02(sv.y + ad.y);
            e2 = leaky02(sv.z + ad.z); e3 = leaky02(sv.w + ad.w);
        }
        float x0 = __expf(e0 - m0), x1 = __expf(e1 - m1);
        float x2 = __expf(e2 - m2), x3 = __expf(e3 - m3);
        if (e < MAXE) {
            ews[e] = x0; ews[MAXE + e] = x1; ews[2 * MAXE + e] = x2; ews[3 * MAXE + e] = x3;
        }
        d0 += x0; d1 += x1; d2 += x2; d3 += x3;
    }
#pragma unroll
    for (int o = 16; o; o >>= 1) {
        d0 += __shfl_xor_sync(full, d0, o);
        d1 += __shfl_xor_sync(full, d1, o);
        d2 += __shfl_xor_sync(full, d2, o);
        d3 += __shfl_xor_sync(full, d3, o);
    }
    float i0 = 1.0f / d0, i1 = 1.0f / d1, i2 = 1.0f / d2, i3 = 1.0f / d3;
    __syncwarp();

    float acc[3][8];
#pragma unroll
    for (int i = 0; i < 3; i++)
#pragma unroll
        for (int k = 0; k < 8; k++) acc[i][k] = 0.0f;

    for (int p = beg; p < end; ++p) {
        int e = p - beg;
        float a0, a1, a2, a3;
        if (e < MAXE) {
            a0 = ews[e] * i0;            a1 = ews[MAXE + e] * i1;
            a2 = ews[2 * MAXE + e] * i2; a3 = ews[3 * MAXE + e] * i3;
        } else {
            int s = g_csrc[p];
            float4 sv = *(const float4*)&asrc[s * 4];
            a0 = __expf(leaky02(sv.x + ad.x) - m0) * i0;
            a1 = __expf(leaky02(sv.y + ad.y) - m1) * i1;
            a2 = __expf(leaky02(sv.z + ad.z) - m2) * i2;
            a3 = __expf(leaky02(sv.w + ad.w) - m3) * i3;
        }
        const uint4* row = (const uint4*)(g_xwh + (size_t)g_csrc[p] * D);
#pragma unroll
        for (int i = 0; i < 3; i++) {
            int idx = i * 256 + lane * 8;
            int h = idx / HD;
            float a = (h == 0) ? a0 : (h == 1) ? a1 : (h == 2) ? a2 : a3;
            uint4 v = __ldg(&row[i * 32 + lane]);
            float2 q0 = __half22float2(*(__half2*)&v.x);
            float2 q1 = __half22float2(*(__half2*)&v.y);
            float2 q2 = __half22float2(*(__half2*)&v.z);
            float2 q3 = __half22float2(*(__half2*)&v.w);
            acc[i][0] = fmaf(a, q0.x, acc[i][0]);
            acc[i][1] = fmaf(a, q0.y, acc[i][1]);
            acc[i][2] = fmaf(a, q1.x, acc[i][2]);
            acc[i][3] = fmaf(a, q1.y, acc[i][3]);
            acc[i][4] = fmaf(a, q2.x, acc[i][4]);
            acc[i][5] = fmaf(a, q2.y, acc[i][5]);
            acc[i][6] = fmaf(a, q3.x, acc[i][6]);
            acc[i][7] = fmaf(a, q3.y, acc[i][7]);
        }
    }

    float s1 = 0.0f;
#pragma unroll
    for (int i = 0; i < 3; i++) {
        int idx = i * 256 + lane * 8;
        float4 b0 = *(const float4*)(bias + idx);
        float4 b1 = *(const float4*)(bias + idx + 4);
        acc[i][0] += b0.x; acc[i][1] += b0.y; acc[i][2] += b0.z; acc[i][3] += b0.w;
        acc[i][4] += b1.x; acc[i][5] += b1.y; acc[i][6] += b1.z; acc[i][7] += b1.w;
#pragma unroll
        for (int k = 0; k < 8; k++) s1 += acc[i][k];
    }
#pragma unroll
    for (int o = 16; o; o >>= 1) s1 += __shfl_xor_sync(full, s1, o);
    float mu = s1 * (1.0f / 768.0f);

    float s2 = 0.0f;
#pragma unroll
    for (int i = 0; i < 3; i++)
#pragma unroll
        for (int k = 0; k < 8; k++) { float dv = acc[i][k] - mu; s2 += dv * dv; }
#pragma unroll
    for (int o = 16; o; o >>= 1) s2 += __shfl_xor_sync(full, s2, o);
    float rstd = rsqrtf(s2 * (1.0f / 768.0f) + 1e-5f);

#pragma unroll
    for (int i = 0; i < 3; i++) {
        int idx = i * 256 + lane * 8;
        float4 g0 = *(const float4*)(gamma + idx);
        float4 g1 = *(const float4*)(gamma + idx + 4);
        float4 e0 = *(const float4*)(beta + idx);
        float4 e1 = *(const float4*)(beta + idx + 4);
        uint4 rv = *(const uint4*)(h_res + (size_t)n * D + idx);
        float2 r0 = __half22float2(*(__half2*)&rv.x);
        float2 r1 = __half22float2(*(__half2*)&rv.y);
        float2 r2 = __half22float2(*(__half2*)&rv.z);
        float2 r3 = __half22float2(*(__half2*)&rv.w);
        out[i][0] = fmaxf(fmaf((acc[i][0] - mu) * rstd, g0.x, e0.x), 0.0f) + r0.x;
        out[i][1] = fmaxf(fmaf((acc[i][1] - mu) * rstd, g0.y, e0.y), 0.0f) + r0.y;
        out[i][2] = fmaxf(fmaf((acc[i][2] - mu) * rstd, g0.z, e0.z), 0.0f) + r1.x;
        out[i][3] = fmaxf(fmaf((acc[i][3] - mu) * rstd, g0.w, e0.w), 0.0f) + r1.y;
        out[i][4] = fmaxf(fmaf((acc[i][4] - mu) * rstd, g1.x, e1.x), 0.0f) + r2.x;
        out[i][5] = fmaxf(fmaf((acc[i][5] - mu) * rstd, g1.y, e1.y), 0.0f) + r2.y;
        out[i][6] = fmaxf(fmaf((acc[i][6] - mu) * rstd, g1.z, e1.z), 0.0f) + r3.x;
        out[i][7] = fmaxf(fmaf((acc[i][7] - mu) * rstd, g1.w, e1.w), 0.0f) + r3.y;
    }
}

// ---------------- layer 1: smem score cache + 1-deep prefetch ----------
__global__ __launch_bounds__(256) void gat_l1_kernel(
    const float* __restrict__ asrc, const float* __restrict__ adst,
    const float* __restrict__ bias, const float* __restrict__ gamma,
    const float* __restrict__ beta, const __half* h_res, __half* h_out)
{
    __shared__ float ews_all[8 * 4 * MAXE];
    const unsigned full = 0xffffffffu;
    int wid  = threadIdx.x >> 5;
    int lane = threadIdx.x & 31;
    int n = blockIdx.x * 8 + wid;
    float* ews = &ews_all[wid * 4 * MAXE];

    int beg = g_rowptr[n], end = g_rowptr[n + 1];
    float4 ad = *(const float4*)&adst[n * 4];

    float m0 = -1e30f, m1 = -1e30f, m2 = -1e30f, m3 = -1e30f;
    for (int p = beg + lane; p < end; p += 32) {
        int s = g_csrc[p];
        float4 sv = *(const float4*)&asrc[s * 4];
        float e0 = leaky02(sv.x + ad.x), e1 = leaky02(sv.y + ad.y);
        float e2 = leaky02(sv.z + ad.z), e3 = leaky02(sv.w + ad.w);
        int e = p - beg;
        if (e < MAXE) {
            ews[e] = e0; ews[MAXE + e] = e1; ews[2 * MAXE + e] = e2; ews[3 * MAXE + e] = e3;
        }
        m0 = fmaxf(m0, e0); m1 = fmaxf(m1, e1); m2 = fmaxf(m2, e2); m3 = fmaxf(m3, e3);
    }
#pragma unroll
    for (int o = 16; o; o >>= 1) {
        m0 = fmaxf(m0, __shfl_xor_sync(full, m0, o));
        m1 = fmaxf(m1, __shfl_xor_sync(full, m1, o));
        m2 = fmaxf(m2, __shfl_xor_sync(full, m2, o));
        m3 = fmaxf(m3, __shfl_xor_sync(full, m3, o));
    }

    float d0 = 0, d1 = 0, d2 = 0, d3 = 0;
    for (int p = beg + lane; p < end; p += 32) {
        int e = p - beg;
        float e0, e1, e2, e3;
        if (e < MAXE) {
            e0 = ews[e]; e1 = ews[MAXE + e]; e2 = ews[2 * MAXE + e]; e3 = ews[3 * MAXE + e];
        } else {
            int s = g_csrc[p];
            float4 sv = *(const float4*)&asrc[s * 4];
            e0 = leaky02(sv.x + ad.x); e1 = leaky02(sv.y + ad.y);
            e2 = leaky02(sv.z + ad.z); e3 = leaky02(sv.w + ad.w);
        }
        float x0 = __expf(e0 - m0), x1 = __expf(e1 - m1);
        float x2 = __expf(e2 - m2), x3 = __expf(e3 - m3);
        if (e < MAXE) {
            ews[e] = x0; ews[MAXE + e] = x1; ews[2 * MAXE + e] = x2; ews[3 * MAXE + e] = x3;
        }
        d0 += x0; d1 += x1; d2 += x2; d3 += x3;
    }
#pragma unroll
    for (int o = 16; o; o >>= 1) {
        d0 += __shfl_xor_sync(full, d0, o);
        d1 += __shfl_xor_sync(full, d1, o);
        d2 += __shfl_xor_sync(full, d2, o);
        d3 += __shfl_xor_sync(full, d3, o);
    }
    float i0 = 1.0f / d0, i1 = 1.0f / d1, i2 = 1.0f / d2, i3 = 1.0f / d3;
    __syncwarp();

    float acc[3][8];
#pragma unroll
    for (int i = 0; i < 3; i++)
#pragma unroll
        for (int k = 0; k < 8; k++) acc[i][k] = 0.0f;

    const uint4* r0p = (const uint4*)(g_xwh + (size_t)g_csrc[beg] * D);
    uint4 f0 = __ldg(&r0p[lane]), f1 = __ldg(&r0p[32 + lane]), f2 = __ldg(&r0p[64 + lane]);

    for (int p = beg; p < end; ++p) {
        uint4 c0 = f0, c1 = f1, c2 = f2;
        int e = p - beg;
        float a0, a1, a2, a3;
        if (e < MAXE) {
            a0 = ews[e] * i0; a1 = ews[MAXE + e] * i1;
            a2 = ews[2 * MAXE + e] * i2; a3 = ews[3 * MAXE + e] * i3;
        } else {
            int s = g_csrc[p];
            float4 sv = *(const float4*)&asrc[s * 4];
            a0 = __expf(leaky02(sv.x + ad.x) - m0) * i0;
            a1 = __expf(leaky02(sv.y + ad.y) - m1) * i1;
            a2 = __expf(leaky02(sv.z + ad.z) - m2) * i2;
            a3 = __expf(leaky02(sv.w + ad.w) - m3) * i3;
        }
        if (p + 1 < end) {
            const uint4* rn = (const uint4*)(g_xwh + (size_t)g_csrc[p + 1] * D);
            f0 = __ldg(&rn[lane]); f1 = __ldg(&rn[32 + lane]); f2 = __ldg(&rn[64 + lane]);
        }
#pragma unroll
        for (int i = 0; i < 3; i++) {
            int idx = i * 256 + lane * 8;
            int h = idx / HD;
            float a = (h == 0) ? a0 : (h == 1) ? a1 : (h == 2) ? a2 : a3;
            uint4 v = (i == 0) ? c0 : (i == 1) ? c1 : c2;
            float2 q0 = __half22float2(*(__half2*)&v.x);
            float2 q1 = __half22float2(*(__half2*)&v.y);
            float2 q2 = __half22float2(*(__half2*)&v.z);
            float2 q3 = __half22float2(*(__half2*)&v.w);
            acc[i][0] = fmaf(a, q0.x, acc[i][0]);
            acc[i][1] = fmaf(a, q0.y, acc[i][1]);
            acc[i][2] = fmaf(a, q1.x, acc[i][2]);
            acc[i][3] = fmaf(a, q1.y, acc[i][3]);
            acc[i][4] = fmaf(a, q2.x, acc[i][4]);
            acc[i][5] = fmaf(a, q2.y, acc[i][5]);
            acc[i][6] = fmaf(a, q3.x, acc[i][6]);
            acc[i][7] = fmaf(a, q3.y, acc[i][7]);
        }
    }

    float s1 = 0.0f;
#pragma unroll
    for (int i = 0; i < 3; i++) {
        int idx = i * 256 + lane * 8;
        float4 b0 = *(const float4*)(bias + idx);
        float4 b1 = *(const float4*)(bias + idx + 4);
        acc[i][0] += b0.x; acc[i][1] += b0.y; acc[i][2] += b0.z; acc[i][3] += b0.w;
        acc[i][4] += b1.x; acc[i][5] += b1.y; acc[i][6] += b1.z; acc[i][7] += b1.w;
#pragma unroll
        for (int k = 0; k < 8; k++) s1 += acc[i][k];
    }
#pragma unroll
    for (int o = 16; o; o >>= 1) s1 += __shfl_xor_sync(full, s1, o);
    float mu = s1 * (1.0f / 768.0f);

    float s2 = 0.0f;
#pragma unroll
    for (int i = 0; i < 3; i++)
#pragma unroll
        for (int k = 0; k < 8; k++) { float dv = acc[i][k] - mu; s2 += dv * dv; }
#pragma unroll
    for (int o = 16; o; o >>= 1) s2 += __shfl_xor_sync(full, s2, o);
    float rstd = rsqrtf(s2 * (1.0f / 768.0f) + 1e-5f);

#pragma unroll
    for (int i = 0; i < 3; i++) {
        int idx = i * 256 + lane * 8;
        float4 g0 = *(const float4*)(gamma + idx);
        float4 g1 = *(const float4*)(gamma + idx + 4);
        float4 e0 = *(const float4*)(beta + idx);
        float4 e1 = *(const float4*)(beta + idx + 4);
        uint4 rv = *(const uint4*)(h_res + (size_t)n * D + idx);
        float2 r0 = __half22float2(*(__half2*)&rv.x);
        float2 r1 = __half22float2(*(__half2*)&rv.y);
        float2 r2 = __half22float2(*(__half2*)&rv.z);
        float2 r3 = __half22float2(*(__half2*)&rv.w);
        float o0 = fmaxf(fmaf((acc[i][0] - mu) * rstd, g0.x, e0.x), 0.0f) + r0.x;
        float o1 = fmaxf(fmaf((acc[i][1] - mu) * rstd, g0.y, e0.y), 0.0f) + r0.y;
        float o2 = fmaxf(fmaf((acc[i][2] - mu) * rstd, g0.z, e0.z), 0.0f) + r1.x;
        float o3 = fmaxf(fmaf((acc[i][3] - mu) * rstd, g0.w, e0.w), 0.0f) + r1.y;
        float o4 = fmaxf(fmaf((acc[i][4] - mu) * rstd, g1.x, e1.x), 0.0f) + r2.x;
        float o5 = fmaxf(fmaf((acc[i][5] - mu) * rstd, g1.y, e1.y), 0.0f) + r2.y;
        float o6 = fmaxf(fmaf((acc[i][6] - mu) * rstd, g1.z, e1.z), 0.0f) + r3.x;
        float o7 = fmaxf(fmaf((acc[i][7] - mu) * rstd, g1.w, e1.w), 0.0f) + r3.y;
        uint4 hv;
        *(__half2*)&hv.x = __floats2half2_rn(o0, o1);
        *(__half2*)&hv.y = __floats2half2_rn(o2, o3);
        *(__half2*)&hv.z = __floats2half2_rn(o4, o5);
        *(__half2*)&hv.w = __floats2half2_rn(o6, o7);
        *(uint4*)(h_out + (size_t)n * D + idx) = hv;
    }
}

// ---------------- layer 2 + pooling fused (score-cached) ----------------
constexpr int SM_L2POOL = 32 * D * 4 + 32 * 4 * MAXE * 4;   // 114,688 B

__global__ __launch_bounds__(1024) void gat_l2_pool_kernel(
    const float* __restrict__ asrc, const float* __restrict__ adst,
    const float* __restrict__ bias, const float* __restrict__ gamma,
    const float* __restrict__ beta, const __half* h_res, __half* pool_out)
{
    extern __shared__ float psm[];
    float* ews_all = psm + 32 * D;
    int wid  = threadIdx.x >> 5;
    int lane = threadIdx.x & 31;
    int n = blockIdx.x * 32 + wid;
    float out[3][8];
    gat_node_compute_cached(n, lane, &ews_all[wid * 4 * MAXE], asrc, adst,
                            bias, gamma, beta, h_res, out);
#pragma unroll
    for (int i = 0; i < 3; i++) {
        int idx = i * 256 + lane * 8;
        *(float4*)&psm[wid * D + idx]     = make_float4(out[i][0], out[i][1], out[i][2], out[i][3]);
        *(float4*)&psm[wid * D + idx + 4] = make_float4(out[i][4], out[i][5], out[i][6], out[i][7]);
    }
    __syncthreads();
    if (threadIdx.x < D) {
        float s = 0.0f;
#pragma unroll
        for (int r = 0; r < 32; r++) s += psm[r * D + threadIdx.x];
        pool_out[(size_t)blockIdx.x * D + threadIdx.x] = __float2half_rn(s * (1.0f / 32.0f));
    }
}

// ---------------- launcher (multi-stream fork/join, graph-capturable) ----------------
extern "C" void kernel_launch(void* const* d_in, const int* in_sizes, int n_in,
                              void* d_out, int out_size)
{
    const float* x   = (const float*)d_in[0];
    const int*   ei  = (const int*)d_in[1];
    const float* W1  = (const float*)d_in[3];
    const float* as1 = (const float*)d_in[4];
    const float* ad1 = (const float*)d_in[5];
    const float* b1  = (const float*)d_in[6];
    const float* g1  = (const float*)d_in[7];
    const float* be1 = (const float*)d_in[8];
    const float* W2  = (const float*)d_in[9];
    const float* as2 = (const float*)d_in[10];
    const float* ad2 = (const float*)d_in[11];
    const float* b2  = (const float*)d_in[12];
    const float* g2  = (const float*)d_in[13];
    const float* be2 = (const float*)d_in[14];
    const float* Wo  = (const float*)d_in[15];
    const float* bo  = (const float*)d_in[16];
    float* out = (float*)d_out;

    float *p_as1, *p_ad1, *p_as2, *p_ad2;
    __half *p_xh, *p_xwh, *p_wt1, *p_wt2, *p_wto, *p_hgh;
    cudaGetSymbolAddress((void**)&p_xh,  g_xh);
    cudaGetSymbolAddress((void**)&p_xwh, g_xwh);
    cudaGetSymbolAddress((void**)&p_wt1, g_wth1);
    cudaGetSymbolAddress((void**)&p_wt2, g_wth2);
    cudaGetSymbolAddress((void**)&p_wto, g_wtho);
    cudaGetSymbolAddress((void**)&p_hgh, g_hgh);
    cudaGetSymbolAddress((void**)&p_as1, g_asrc1);
    cudaGetSymbolAddress((void**)&p_ad1, g_adst1);
    cudaGetSymbolAddress((void**)&p_as2, g_asrc2);
    cudaGetSymbolAddress((void**)&p_ad2, g_adst2);

    cudaFuncSetAttribute(mma_gemm_kernel,
                         cudaFuncAttributeMaxDynamicSharedMemorySize, SM_GEMM);
    cudaFuncSetAttribute(gat_l2_pool_kernel,
                         cudaFuncAttributeMaxDynamicSharedMemorySize, SM_L2POOL);

    static cudaStream_t s2 = nullptr;
    static cudaEvent_t evFork = nullptr, evW1 = nullptr, evSide = nullptr;
    if (!s2) {
        cudaStreamCreateWithFlags(&s2, cudaStreamNonBlocking);
        cudaEventCreateWithFlags(&evFork, cudaEventDisableTiming);
        cudaEventCreateWithFlags(&evW1, cudaEventDisableTiming);
        cudaEventCreateWithFlags(&evSide, cudaEventDisableTiming);
    }

    dim3 tgrid(24, 24), tblk(32, 8);
    dim3 ggrid(D / 128, NN / 128);     // (6, 1024)

    // ---- fork ----
    cudaEventRecord(evFork, 0);
    cudaStreamWaitEvent(s2, evFork, 0);
    // side: GEMM-1 prerequisites first, then the rest
    transpose768_kernel<<<tgrid, tblk, 0, s2>>>(W1, p_wt1);
    zero_attn_kernel<<<(NN * HH) / 256, 256, 0, s2>>>(p_as1, p_ad1);
    cudaEventRecord(evW1, s2);
    transpose768_kernel<<<tgrid, tblk, 0, s2>>>(W2, p_wt2);
    transpose768_kernel<<<tgrid, tblk, 0, s2>>>(Wo, p_wto);
    zero_attn_kernel<<<(NN * HH) / 256, 256, 0, s2>>>(p_as2, p_ad2);
    init_indeg_kernel<<<NN / 256, 256, 0, s2>>>();
    count_deg_kernel<<<EE / 256, 256, 0, s2>>>(ei);
    scan_phase1_kernel<<<NN / 1024, 1024, 0, s2>>>();
    scan_phase2_kernel<<<1, 128, 0, s2>>>();
    scan3_selfloop_kernel<<<(NN + 255) / 256, 256, 0, s2>>>();
    scatter_edges_kernel<<<EE / 256, 256, 0, s2>>>(ei);
    cudaEventRecord(evSide, s2);

    // ---- main: conv -> (wait W1 prereqs) -> GEMM1 ----
    conv_half_kernel<<<(NN * (D / 4)) / 256, 256>>>((const float4*)x, (__half2*)p_xh);
    cudaStreamWaitEvent(0, evW1, 0);
    mma_gemm_kernel<<<ggrid, 256, SM_GEMM>>>(p_xh, p_wt1, nullptr, p_xwh, nullptr,
                                             as1, ad1, p_as1, p_ad1);

    // ---- join: CSR + W2/Wo + layer-2 score buffers ready ----
    cudaStreamWaitEvent(0, evSide, 0);

    // layer 1 (in-place fp16 h1 into g_xh)
    gat_l1_kernel<<<NN / 8, 256>>>(p_as1, p_ad1, b1, g1, be1, p_xh, p_xh);

    // layer 2 (own score buffers — no zeroing on critical path)
    mma_gemm_kernel<<<ggrid, 256, SM_GEMM>>>(p_xh, p_wt2, nullptr, p_xwh, nullptr,
                                             as2, ad2, p_as2, p_ad2);
    gat_l2_pool_kernel<<<GG, 1024, SM_L2POOL>>>(p_as2, p_ad2, b2, g2, be2, p_xh, p_hgh);

    // output projection (fp32 out + bias)
    mma_gemm_kernel<<<dim3(D / 128, GG / 128), 256, SM_GEMM>>>(p_hgh, p_wto, out, nullptr, bo,
                                                               nullptr, nullptr, nullptr, nullptr);
}